// round 2
// baseline (speedup 1.0000x reference)
#include <cuda_runtime.h>
#include <cstdint>

// Fixed shapes from reference setup_inputs
#define Bn 8
#define Nn 64
#define Vn 128000
#define NVn (Nn*Vn)          // 8,192,000 elements per batch row
#define Kk 64
#define FINE_BASE 0x3F000000u   // float bits of 0.5
#define FINE_BINS 4096          // 2^11-ulp bins over [0.5, 1)
#define CAP 16384               // per-batch candidate capacity
#define BLK_PER_B 128
#define THREADS 256
#define TARGET_CAND 1536.0f     // expected speculative candidate count

// Static device scratch (no allocations allowed)
__device__ unsigned g_hist[Bn][FINE_BINS];
__device__ unsigned g_cnt[Bn];
__device__ unsigned g_cut[Bn];       // per-batch speculative cut (float bits)
__device__ unsigned g_thresh[Bn];    // exact (bin-floor) threshold bits
__device__ unsigned g_fallback[Bn];
__device__ unsigned long long g_cand[Bn][CAP];

// ---------------------------------------------------------------------------
// Kernel 0: zero scratch (graph-replay safe)
// ---------------------------------------------------------------------------
__global__ void kzero() {
    unsigned i = blockIdx.x * blockDim.x + threadIdx.x;
    if (i < Bn * FINE_BINS) ((unsigned*)g_hist)[i] = 0;
    if (i < Bn) { g_cnt[i] = 0; g_fallback[i] = 0; g_thresh[i] = 0; }
}

// ---------------------------------------------------------------------------
// Kernel 0.5: per-batch adaptive speculative cut.
// Solve  V * sum_n max(0, 1 - z/p_n) = TARGET_CAND  by bisection on z.
// Expected candidates above cut ~ TARGET_CAND >> K, << CAP.
// ---------------------------------------------------------------------------
__global__ void kprep(const float* __restrict__ parent) {
    const int b = blockIdx.x;
    __shared__ float p[Nn];
    if (threadIdx.x < Nn) p[threadIdx.x] = parent[b * Nn + threadIdx.x];
    __syncthreads();
    if (threadIdx.x == 0) {
        float pmax = 0.0f;
        #pragma unroll
        for (int n = 0; n < Nn; n++) pmax = fmaxf(pmax, p[n]);
        float lo = 0.0f, hi = pmax;
        for (int it = 0; it < 40; it++) {
            float mid = 0.5f * (lo + hi);
            float cnt = 0.0f;
            for (int n = 0; n < Nn; n++) {
                float t = 1.0f - mid / p[n];
                if (t > 0.0f) cnt += t;
            }
            cnt *= (float)Vn;
            if (cnt > TARGET_CAND) lo = mid; else hi = mid;
        }
        // lo: expected count >= TARGET_CAND above it
        g_cut[b] = __float_as_uint(lo);
    }
}

// ---------------------------------------------------------------------------
// Kernel 1: single streaming pass.
//  - p = sampled * parent (fp32, identical rounding to reference)
//  - histogram of float bits over [0.5,1) (exactness insurance)
//  - speculative candidate append for p >= cut_b
//  key = (bits<<32) | ~flat_idx  -> desc sort == value desc, index asc
// ---------------------------------------------------------------------------
__global__ void kpass1(const float* __restrict__ sampled,
                       const float* __restrict__ parent) {
    __shared__ unsigned sh[FINE_BINS];
    const int b = blockIdx.y;
    for (int i = threadIdx.x; i < FINE_BINS; i += THREADS) sh[i] = 0;
    __syncthreads();

    const unsigned cut = g_cut[b];
    const float4* src = (const float4*)(sampled + (size_t)b * NVn);
    const float*  par = parent + b * Nn;
    const int n4 = NVn / 4;           // 2,048,000

    for (int i4 = blockIdx.x * THREADS + threadIdx.x; i4 < n4;
         i4 += BLK_PER_B * THREADS) {
        float4 x = src[i4];
        float pp = __ldg(par + i4 / (Vn / 4));
        unsigned base = 4u * (unsigned)i4;
        float v[4] = {x.x, x.y, x.z, x.w};
        #pragma unroll
        for (int j = 0; j < 4; j++) {
            unsigned bits = __float_as_uint(v[j] * pp);   // >= 0 always
            if (bits >= FINE_BASE) {
                unsigned bin = (bits - FINE_BASE) >> 11;
                if (bin >= FINE_BINS) bin = FINE_BINS - 1;
                atomicAdd(&sh[bin], 1u);
            }
            if (bits >= cut) {
                unsigned pos = atomicAdd(&g_cnt[b], 1u);
                if (pos < CAP) {
                    g_cand[b][pos] =
                        ((unsigned long long)bits << 32) |
                        (unsigned long long)(0xFFFFFFFFu - (base + j));
                }
            }
        }
    }
    __syncthreads();
    for (int i = threadIdx.x; i < FINE_BINS; i += THREADS) {
        unsigned c = sh[i];
        if (c) atomicAdd(&g_hist[b][i], c);
    }
}

// ---------------------------------------------------------------------------
// Kernel 2: exact bin-floor threshold from histogram; validate speculation.
// Valid iff: bin-floor(threshold) >= cut  AND  cnt <= CAP.
// ---------------------------------------------------------------------------
__global__ void kthresh() {
    const int b = blockIdx.x;
    __shared__ unsigned s[THREADS];
    unsigned sum = 0;
    const int per = FINE_BINS / THREADS;   // 16
    #pragma unroll
    for (int j = 0; j < per; j++) sum += g_hist[b][threadIdx.x * per + j];
    s[threadIdx.x] = sum;
    __syncthreads();
    if (threadIdx.x == 0) {
        unsigned cum = 0;
        int t = -1;
        for (int c = THREADS - 1; c >= 0; c--) {
            if (cum + s[c] >= Kk) {
                for (int bin = c * per + per - 1; bin >= c * per; bin--) {
                    cum += g_hist[b][bin];
                    if (cum >= Kk) { t = bin; break; }
                }
                break;
            }
            cum += s[c];
        }
        unsigned thresh = (t >= 0) ? (FINE_BASE + ((unsigned)t << 11)) : 0u;
        g_thresh[b] = thresh;
        unsigned cnt = g_cnt[b];
        if (t >= 0 && thresh >= g_cut[b] && cnt <= CAP) {
            g_fallback[b] = 0;   // candidates are a superset of the top-K
        } else {
            g_fallback[b] = 1;   // exact re-collect
            g_cnt[b] = 0;
        }
    }
}

// ---------------------------------------------------------------------------
// Kernel 3: fallback collect with exact threshold (normally exits instantly).
// ---------------------------------------------------------------------------
__global__ void kcollect(const float* __restrict__ sampled,
                         const float* __restrict__ parent) {
    const int b = blockIdx.y;
    if (g_fallback[b] == 0) return;
    const unsigned thresh = g_thresh[b];
    const float4* src = (const float4*)(sampled + (size_t)b * NVn);
    const float*  par = parent + b * Nn;
    const int n4 = NVn / 4;
    for (int i4 = blockIdx.x * THREADS + threadIdx.x; i4 < n4;
         i4 += BLK_PER_B * THREADS) {
        float4 x = src[i4];
        float pp = __ldg(par + i4 / (Vn / 4));
        unsigned base = 4u * (unsigned)i4;
        float v[4] = {x.x, x.y, x.z, x.w};
        #pragma unroll
        for (int j = 0; j < 4; j++) {
            unsigned bits = __float_as_uint(v[j] * pp);
            if (bits >= thresh) {
                unsigned pos = atomicAdd(&g_cnt[b], 1u);
                if (pos < CAP) {
                    g_cand[b][pos] =
                        ((unsigned long long)bits << 32) |
                        (unsigned long long)(0xFFFFFFFFu - (base + j));
                }
            }
        }
    }
}

// ---------------------------------------------------------------------------
// Kernel 4: per-batch top-K by repeated block argmax.
// Output: 1536 float32 = [token_ids (B*K)] [topk_probs (B*K)] [parents (B*K)]
// (JAX type promotion: int64 + float32 -> float32)
// ---------------------------------------------------------------------------
__global__ void kselect(float* __restrict__ out) {
    const int b = blockIdx.x;
    unsigned cnt = g_cnt[b];
    if (cnt > CAP) cnt = CAP;

    __shared__ unsigned long long buf[4096];
    __shared__ unsigned long long warpmax[8];
    __shared__ unsigned long long sel[Kk];

    const bool use_sh = (cnt <= 4096);
    unsigned long long* arr = use_sh ? buf : g_cand[b];
    if (use_sh) {
        for (unsigned i = threadIdx.x; i < cnt; i += THREADS)
            buf[i] = g_cand[b][i];
    }
    __syncthreads();

    for (int j = 0; j < Kk; j++) {
        unsigned long long m = 0ull;
        int mpos = -1;
        for (unsigned i = threadIdx.x; i < cnt; i += THREADS) {
            unsigned long long v = arr[i];
            if (v > m) { m = v; mpos = (int)i; }
        }
        unsigned long long wm = m;
        #pragma unroll
        for (int o = 16; o; o >>= 1) {
            unsigned long long o2 = __shfl_down_sync(0xFFFFFFFFu, wm, o);
            if (o2 > wm) wm = o2;
        }
        if ((threadIdx.x & 31) == 0) warpmax[threadIdx.x >> 5] = wm;
        __syncthreads();
        if (threadIdx.x == 0) {
            unsigned long long g = warpmax[0];
            #pragma unroll
            for (int w = 1; w < 8; w++) if (warpmax[w] > g) g = warpmax[w];
            warpmax[0] = g;
            sel[j] = g;
        }
        __syncthreads();
        unsigned long long gm = warpmax[0];
        if (mpos >= 0 && m == gm) arr[mpos] = 0ull;  // keys unique: one owner
        __syncthreads();
    }

    if (threadIdx.x < Kk) {
        int j = threadIdx.x;
        unsigned long long key = sel[j];
        unsigned tok = 0, parenti = 0;
        float prob = 0.0f;
        if (key != 0ull) {
            unsigned idx = 0xFFFFFFFFu - (unsigned)(key & 0xFFFFFFFFull);
            parenti = idx / Vn;
            tok = idx - parenti * Vn;
            prob = __uint_as_float((unsigned)(key >> 32));
        }
        out[b * Kk + j]               = (float)tok;
        out[Bn * Kk + b * Kk + j]     = prob;
        out[2 * Bn * Kk + b * Kk + j] = (float)parenti;
    }
}

// ---------------------------------------------------------------------------
extern "C" void kernel_launch(void* const* d_in, const int* in_sizes, int n_in,
                              void* d_out, int out_size) {
    const float* sampled = (const float*)d_in[0];  // [B, N, V] fp32
    const float* parent  = (const float*)d_in[1];  // [B, N]    fp32
    float* out = (float*)d_out;                    // 3 * B * K float32

    (void)in_sizes; (void)n_in; (void)out_size;

    kzero<<<(Bn * FINE_BINS + THREADS - 1) / THREADS, THREADS>>>();
    kprep<<<Bn, 64>>>(parent);
    dim3 g(BLK_PER_B, Bn);
    kpass1<<<g, THREADS>>>(sampled, parent);
    kthresh<<<Bn, THREADS>>>();
    kcollect<<<g, THREADS>>>(sampled, parent);
    kselect<<<Bn, THREADS>>>(out);
}

// round 3
// speedup vs baseline: 1.8905x; 1.8905x over previous
#include <cuda_runtime.h>
#include <cstdint>

// Fixed shapes from reference setup_inputs
#define Bn 8
#define Nn 64
#define Vn 128000
#define Kk 64
#define CAP 16384
#define ROW_F4 32000          // float4 per (b,n) row (V/4)
#define TARGET 2048.0f        // expected speculative candidate count per batch
#define FBBINS 16384          // fallback histogram bins (bits >> 16)

// Static device scratch (no allocations allowed)
__device__ float g_cutf[Bn];            // per-batch cut in product domain
__device__ float g_cutdiv[Bn * Nn];     // per-(b,n) conservative cut in v domain
__device__ unsigned g_cnt[Bn];
__device__ unsigned g_fallback[Bn];
__device__ unsigned long long g_cand[Bn][CAP];
__device__ unsigned g_fbhist[Bn][FBBINS];

// ---------------------------------------------------------------------------
// Kernel 1: per-batch adaptive cut by warp-parallel bisection on
//   V * sum_n max(0, 1 - z/p_n) = TARGET.  Also zeros per-batch state.
// ---------------------------------------------------------------------------
__global__ void kprep(const float* __restrict__ parent) {
    const int b = blockIdx.x;
    const int l = threadIdx.x;                 // 0..31, each owns 2 leaves
    float p0 = parent[b * Nn + l];
    float p1 = parent[b * Nn + 32 + l];
    float inv0 = 1.0f / p0;                    // inf if p==0 (handled below)
    float inv1 = 1.0f / p1;

    float pm = fmaxf(p0, p1);
    #pragma unroll
    for (int o = 16; o; o >>= 1) pm = fmaxf(pm, __shfl_xor_sync(0xFFFFFFFFu, pm, o));

    float lo = 0.0f, hi = pm;
    for (int it = 0; it < 28; it++) {
        float mid = 0.5f * (lo + hi);
        float t = fmaxf(0.0f, 1.0f - mid * inv0) + fmaxf(0.0f, 1.0f - mid * inv1);
        #pragma unroll
        for (int o = 16; o; o >>= 1) t += __shfl_xor_sync(0xFFFFFFFFu, t, o);
        if (t * (float)Vn > TARGET) lo = mid; else hi = mid;
    }
    const float cutf = lo;
    if (l == 0) { g_cutf[b] = cutf; g_cnt[b] = 0; g_fallback[b] = 0; }
    const float SAFE = 0.999999f;   // covers fp rounding of mul/div chain
    g_cutdiv[b * Nn + l]      = cutf * inv0 * SAFE;
    g_cutdiv[b * Nn + 32 + l] = cutf * inv1 * SAFE;
}

// ---------------------------------------------------------------------------
// Candidate push (rare path). key = bits<<32 | ~flat_idx : desc order ==
// value desc, index asc == exact jax.lax.top_k tie-break.
// ---------------------------------------------------------------------------
__device__ __forceinline__ void push(int b, unsigned bits, unsigned idx) {
    unsigned pos = atomicAdd(&g_cnt[b], 1u);
    if (pos < CAP)
        g_cand[b][pos] = ((unsigned long long)bits << 32) |
                         (unsigned long long)(0xFFFFFFFFu - idx);
}

__device__ __forceinline__ void appendf4(int b, float4 x, float pp, float cutf,
                                         unsigned colbase, int i4, bool valid) {
    if (!valid) return;
    unsigned c = colbase + 4u * (unsigned)i4;
    float p0 = x.x * pp, p1 = x.y * pp, p2 = x.z * pp, p3 = x.w * pp;
    if (p0 >= cutf) push(b, __float_as_uint(p0), c + 0);
    if (p1 >= cutf) push(b, __float_as_uint(p1), c + 1);
    if (p2 >= cutf) push(b, __float_as_uint(p2), c + 2);
    if (p3 >= cutf) push(b, __float_as_uint(p3), c + 3);
}

// ---------------------------------------------------------------------------
// Kernel 2: streaming max-screen pass. Grid: (8 chunks, 512 rows).
// Each thread handles 4 groups of 4 coalesced float4s (64 elements total).
// Fast path per 16-element group: 4 LDG.128 + 15 FMNMX + 1 FSETP.
// ---------------------------------------------------------------------------
__global__ __launch_bounds__(256) void kpass1(const float* __restrict__ sampled,
                                              const float* __restrict__ parent) {
    const int row = blockIdx.y;               // b*64 + n
    const int b = row >> 6;
    const float pp = parent[row];
    const float cutv = g_cutdiv[row];
    const float cutf = g_cutf[b];
    const float4* src = (const float4*)sampled + (size_t)row * ROW_F4;
    const unsigned colbase = (unsigned)(row & 63) * (unsigned)Vn;
    const int cb = blockIdx.x * 4096 + threadIdx.x;
    const bool full = (blockIdx.x != 7);       // last chunk is partial (32000 vs 32768)

    #pragma unroll
    for (int g = 0; g < 4; g++) {
        const int i0 = cb + g * 1024;
        float4 x0, x1, x2, x3;
        bool v0 = true, v1 = true, v2 = true, v3 = true;
        if (full) {
            x0 = src[i0];       x1 = src[i0 + 256];
            x2 = src[i0 + 512]; x3 = src[i0 + 768];
        } else {
            v0 = i0 < ROW_F4;       v1 = i0 + 256 < ROW_F4;
            v2 = i0 + 512 < ROW_F4; v3 = i0 + 768 < ROW_F4;
            x0 = v0 ? src[i0]       : make_float4(0.f, 0.f, 0.f, 0.f);
            x1 = v1 ? src[i0 + 256] : make_float4(0.f, 0.f, 0.f, 0.f);
            x2 = v2 ? src[i0 + 512] : make_float4(0.f, 0.f, 0.f, 0.f);
            x3 = v3 ? src[i0 + 768] : make_float4(0.f, 0.f, 0.f, 0.f);
        }
        float m0 = fmaxf(fmaxf(x0.x, x0.y), fmaxf(x0.z, x0.w));
        float m1 = fmaxf(fmaxf(x1.x, x1.y), fmaxf(x1.z, x1.w));
        float m2 = fmaxf(fmaxf(x2.x, x2.y), fmaxf(x2.z, x2.w));
        float m3 = fmaxf(fmaxf(x3.x, x3.y), fmaxf(x3.z, x3.w));
        float m = fmaxf(fmaxf(m0, m1), fmaxf(m2, m3));
        if (m >= cutv) {   // rare (~0.05% of groups)
            appendf4(b, x0, pp, cutf, colbase, i0,       v0);
            appendf4(b, x1, pp, cutf, colbase, i0 + 256, v1);
            appendf4(b, x2, pp, cutf, colbase, i0 + 512, v2);
            appendf4(b, x3, pp, cutf, colbase, i0 + 768, v3);
        }
    }
}

// ---------------------------------------------------------------------------
// Kernel 3: validate speculation per batch.
// ---------------------------------------------------------------------------
__global__ void kcheck() {
    int b = threadIdx.x;
    if (b < Bn) {
        unsigned c = g_cnt[b];
        g_fallback[b] = (c < Kk || c > CAP) ? 1u : 0u;
    }
}

// ---------------------------------------------------------------------------
// Kernel 4: exact fallback (normally exits immediately). One block per batch:
// histogram over bits>>16, exact bin-floor threshold, re-collect.
// ---------------------------------------------------------------------------
__global__ void kfallback(const float* __restrict__ sampled,
                          const float* __restrict__ parent) {
    const int b = blockIdx.x;
    if (g_fallback[b] == 0) return;            // uniform per block

    if (threadIdx.x == 0) g_cnt[b] = 0;
    for (int i = threadIdx.x; i < FBBINS; i += 256) g_fbhist[b][i] = 0;
    __syncthreads();

    const float* rowp = sampled + (size_t)b * Nn * Vn;
    const float* par = parent + b * Nn;
    for (int i = threadIdx.x; i < Nn * Vn; i += 256) {
        float p = rowp[i] * par[i / Vn];
        unsigned bin = __float_as_uint(p) >> 16;
        if (bin >= FBBINS) bin = FBBINS - 1;
        atomicAdd(&g_fbhist[b][bin], 1u);
    }
    __syncthreads();

    __shared__ unsigned s_th;
    if (threadIdx.x == 0) {
        unsigned cum = 0; unsigned t = 0;
        for (int bin = FBBINS - 1; bin >= 0; bin--) {
            cum += g_fbhist[b][bin];
            if (cum >= Kk) { t = (unsigned)bin; break; }
        }
        s_th = t << 16;
    }
    __syncthreads();
    const unsigned th = s_th;
    for (int i = threadIdx.x; i < Nn * Vn; i += 256) {
        float p = rowp[i] * par[i / Vn];
        unsigned bits = __float_as_uint(p);
        if (bits >= th) push(b, bits, (unsigned)i);
    }
}

// ---------------------------------------------------------------------------
// Kernel 5: per-batch top-K by repeated block argmax.
// Output: 1536 float32 = [token_ids B*K][topk_probs B*K][parents B*K]
// ---------------------------------------------------------------------------
__global__ void kselect(float* __restrict__ out) {
    const int b = blockIdx.x;
    unsigned cnt = g_cnt[b];
    if (cnt > CAP) cnt = CAP;

    __shared__ unsigned long long buf[4096];
    __shared__ unsigned long long warpmax[8];
    __shared__ unsigned long long sel[Kk];

    const bool use_sh = (cnt <= 4096);
    unsigned long long* arr = use_sh ? buf : g_cand[b];
    if (use_sh) {
        for (unsigned i = threadIdx.x; i < cnt; i += 256)
            buf[i] = g_cand[b][i];
    }
    __syncthreads();

    for (int j = 0; j < Kk; j++) {
        unsigned long long m = 0ull;
        int mpos = -1;
        for (unsigned i = threadIdx.x; i < cnt; i += 256) {
            unsigned long long v = arr[i];
            if (v > m) { m = v; mpos = (int)i; }
        }
        unsigned long long wm = m;
        #pragma unroll
        for (int o = 16; o; o >>= 1) {
            unsigned long long o2 = __shfl_down_sync(0xFFFFFFFFu, wm, o);
            if (o2 > wm) wm = o2;
        }
        if ((threadIdx.x & 31) == 0) warpmax[threadIdx.x >> 5] = wm;
        __syncthreads();
        if (threadIdx.x == 0) {
            unsigned long long g2 = warpmax[0];
            #pragma unroll
            for (int w = 1; w < 8; w++) if (warpmax[w] > g2) g2 = warpmax[w];
            warpmax[0] = g2;
            sel[j] = g2;
        }
        __syncthreads();
        unsigned long long gm = warpmax[0];
        if (mpos >= 0 && m == gm) arr[mpos] = 0ull;   // keys unique: one owner
        __syncthreads();
    }

    if (threadIdx.x < Kk) {
        int j = threadIdx.x;
        unsigned long long key = sel[j];
        unsigned tok = 0, parenti = 0;
        float prob = 0.0f;
        if (key != 0ull) {
            unsigned idx = 0xFFFFFFFFu - (unsigned)(key & 0xFFFFFFFFull);
            parenti = idx / Vn;
            tok = idx - parenti * Vn;
            prob = __uint_as_float((unsigned)(key >> 32));
        }
        out[b * Kk + j]               = (float)tok;
        out[Bn * Kk + b * Kk + j]     = prob;
        out[2 * Bn * Kk + b * Kk + j] = (float)parenti;
    }
}

// ---------------------------------------------------------------------------
extern "C" void kernel_launch(void* const* d_in, const int* in_sizes, int n_in,
                              void* d_out, int out_size) {
    const float* sampled = (const float*)d_in[0];  // [B, N, V] fp32
    const float* parent  = (const float*)d_in[1];  // [B, N]    fp32
    float* out = (float*)d_out;                    // 3 * B * K float32

    (void)in_sizes; (void)n_in; (void)out_size;

    kprep<<<Bn, 32>>>(parent);
    dim3 g(8, Bn * Nn);
    kpass1<<<g, 256>>>(sampled, parent);
    kcheck<<<1, 32>>>();
    kfallback<<<Bn, 256>>>(sampled, parent);
    kselect<<<Bn, 256>>>(out);
}

// round 4
// speedup vs baseline: 3.9704x; 2.1002x over previous
#include <cuda_runtime.h>
#include <cstdint>

// Fixed shapes from reference setup_inputs
#define Bn 8
#define Nn 64
#define Vn 128000
#define Kk 64
#define CAP 16384
#define ROW_F4 32000          // float4 per (b,n) row (V/4)
#define TARGET 512.0f         // expected speculative candidate count per batch

// Static device scratch (no allocations allowed)
__device__ float g_cutf[Bn];            // per-batch cut in product domain
__device__ float g_cutdiv[Bn * Nn];     // per-(b,n) conservative cut in v domain
__device__ unsigned g_cnt[Bn];
__device__ unsigned long long g_cand[Bn][CAP];

// ---------------------------------------------------------------------------
// Kernel 1: per-batch adaptive cut by warp-parallel bisection on
//   V * sum_n max(0, 1 - z/p_n) = TARGET.  Also zeros per-batch state.
// Rows with p_n <= cutf get cutdiv >= 1  ->  provably no candidates
// (v < 1 always), so kpass1 skips them without reading.
// ---------------------------------------------------------------------------
__global__ void kprep(const float* __restrict__ parent) {
    const int b = blockIdx.x;
    const int l = threadIdx.x;                 // 0..31, each owns 2 leaves
    float p0 = parent[b * Nn + l];
    float p1 = parent[b * Nn + 32 + l];
    float inv0 = 1.0f / p0;
    float inv1 = 1.0f / p1;

    float pm = fmaxf(p0, p1);
    #pragma unroll
    for (int o = 16; o; o >>= 1) pm = fmaxf(pm, __shfl_xor_sync(0xFFFFFFFFu, pm, o));

    float lo = 0.0f, hi = pm;
    for (int it = 0; it < 28; it++) {
        float mid = 0.5f * (lo + hi);
        float t = fmaxf(0.0f, 1.0f - mid * inv0) + fmaxf(0.0f, 1.0f - mid * inv1);
        #pragma unroll
        for (int o = 16; o; o >>= 1) t += __shfl_xor_sync(0xFFFFFFFFu, t, o);
        if (t * (float)Vn > TARGET) lo = mid; else hi = mid;
    }
    const float cutf = lo;
    if (l == 0) { g_cutf[b] = cutf; g_cnt[b] = 0; }
    const float SAFE = 0.999999f;   // covers fp rounding of the mul/div chain
    g_cutdiv[b * Nn + l]      = cutf * inv0 * SAFE;
    g_cutdiv[b * Nn + 32 + l] = cutf * inv1 * SAFE;
}

// ---------------------------------------------------------------------------
// Candidate push. key = bits<<32 | ~flat_idx : descending key order ==
// value desc, index asc == exact jax.lax.top_k tie-break.
// ---------------------------------------------------------------------------
__device__ __forceinline__ void push(int b, unsigned bits, unsigned idx) {
    unsigned pos = atomicAdd(&g_cnt[b], 1u);
    if (pos < CAP)
        g_cand[b][pos] = ((unsigned long long)bits << 32) |
                         (unsigned long long)(0xFFFFFFFFu - idx);
}

// ---------------------------------------------------------------------------
// Kernel 2: row-skipping collect. Grid (16, 512): 16 chunks per (b,n) row.
// Rows with cutdiv >= 1 exit without touching sampled[] (typ. 61/64 rows).
// Active rows: float4 load + 3 FMNMX screen; rare slow path does exact
// products and pushes candidates.
// ---------------------------------------------------------------------------
__global__ __launch_bounds__(256) void kpass1(const float* __restrict__ sampled,
                                              const float* __restrict__ parent) {
    const int row = blockIdx.y;               // b*64 + n
    const float cutv = g_cutdiv[row];
    if (!(cutv < 1.0f)) return;               // skip row (also skips inf/nan)

    const int b = row >> 6;
    const float pp = parent[row];
    const float cutf = g_cutf[b];
    const float4* src = (const float4*)sampled + (size_t)row * ROW_F4;
    const unsigned colbase = (unsigned)(row & 63) * (unsigned)Vn;

    for (int i = blockIdx.x * 256 + threadIdx.x; i < ROW_F4; i += 16 * 256) {
        float4 x = src[i];
        float m = fmaxf(fmaxf(x.x, x.y), fmaxf(x.z, x.w));
        if (m >= cutv) {                      // rare
            unsigned c = colbase + 4u * (unsigned)i;
            float q0 = x.x * pp, q1 = x.y * pp, q2 = x.z * pp, q3 = x.w * pp;
            if (q0 >= cutf) push(b, __float_as_uint(q0), c + 0);
            if (q1 >= cutf) push(b, __float_as_uint(q1), c + 1);
            if (q2 >= cutf) push(b, __float_as_uint(q2), c + 2);
            if (q3 >= cutf) push(b, __float_as_uint(q3), c + 3);
        }
    }
}

// ---------------------------------------------------------------------------
// Kernel 3: exact fallback; self-guarded (no-op when speculation valid).
// One block per batch: coarse histogram -> exact bin-floor threshold ->
// re-collect. Statistically never runs; correctness backstop only.
// ---------------------------------------------------------------------------
#define FBBINS 16384
__device__ unsigned g_fbhist[Bn][FBBINS];

__global__ void kfallback(const float* __restrict__ sampled,
                          const float* __restrict__ parent) {
    const int b = blockIdx.x;
    {
        unsigned c = g_cnt[b];
        if (c >= Kk && c <= CAP) return;       // speculation valid (uniform)
    }
    if (threadIdx.x == 0) g_cnt[b] = 0;
    for (int i = threadIdx.x; i < FBBINS; i += 256) g_fbhist[b][i] = 0;
    __syncthreads();

    const float* rowp = sampled + (size_t)b * Nn * Vn;
    const float* par = parent + b * Nn;
    for (int i = threadIdx.x; i < Nn * Vn; i += 256) {
        float p = rowp[i] * par[i / Vn];
        unsigned bin = __float_as_uint(p) >> 16;
        if (bin >= FBBINS) bin = FBBINS - 1;
        atomicAdd(&g_fbhist[b][bin], 1u);
    }
    __syncthreads();

    __shared__ unsigned s_th;
    if (threadIdx.x == 0) {
        unsigned cum = 0; unsigned t = 0;
        for (int bin = FBBINS - 1; bin >= 0; bin--) {
            cum += g_fbhist[b][bin];
            if (cum >= Kk) { t = (unsigned)bin; break; }
        }
        s_th = t << 16;
    }
    __syncthreads();
    const unsigned th = s_th;
    for (int i = threadIdx.x; i < Nn * Vn; i += 256) {
        float p = rowp[i] * par[i / Vn];
        unsigned bits = __float_as_uint(p);
        if (bits >= th) push(b, bits, (unsigned)i);
    }
}

// ---------------------------------------------------------------------------
// Kernel 4: per-batch top-K by repeated block argmax (cnt ~512 typically).
// Output: 1536 float32 = [token_ids B*K][topk_probs B*K][parents B*K]
// ---------------------------------------------------------------------------
__global__ void kselect(float* __restrict__ out) {
    const int b = blockIdx.x;
    unsigned cnt = g_cnt[b];
    if (cnt > CAP) cnt = CAP;

    __shared__ unsigned long long buf[4096];
    __shared__ unsigned long long warpmax[8];
    __shared__ unsigned long long sel[Kk];

    const bool use_sh = (cnt <= 4096);
    unsigned long long* arr = use_sh ? buf : g_cand[b];
    if (use_sh) {
        for (unsigned i = threadIdx.x; i < cnt; i += 256)
            buf[i] = g_cand[b][i];
    }
    __syncthreads();

    for (int j = 0; j < Kk; j++) {
        unsigned long long m = 0ull;
        int mpos = -1;
        for (unsigned i = threadIdx.x; i < cnt; i += 256) {
            unsigned long long v = arr[i];
            if (v > m) { m = v; mpos = (int)i; }
        }
        unsigned long long wm = m;
        #pragma unroll
        for (int o = 16; o; o >>= 1) {
            unsigned long long o2 = __shfl_down_sync(0xFFFFFFFFu, wm, o);
            if (o2 > wm) wm = o2;
        }
        if ((threadIdx.x & 31) == 0) warpmax[threadIdx.x >> 5] = wm;
        __syncthreads();
        if (threadIdx.x == 0) {
            unsigned long long g2 = warpmax[0];
            #pragma unroll
            for (int w = 1; w < 8; w++) if (warpmax[w] > g2) g2 = warpmax[w];
            warpmax[0] = g2;
            sel[j] = g2;
        }
        __syncthreads();
        unsigned long long gm = warpmax[0];
        if (mpos >= 0 && m == gm) arr[mpos] = 0ull;   // keys unique: one owner
        __syncthreads();
    }

    if (threadIdx.x < Kk) {
        int j = threadIdx.x;
        unsigned long long key = sel[j];
        unsigned tok = 0, parenti = 0;
        float prob = 0.0f;
        if (key != 0ull) {
            unsigned idx = 0xFFFFFFFFu - (unsigned)(key & 0xFFFFFFFFull);
            parenti = idx / Vn;
            tok = idx - parenti * Vn;
            prob = __uint_as_float((unsigned)(key >> 32));
        }
        out[b * Kk + j]               = (float)tok;
        out[Bn * Kk + b * Kk + j]     = prob;
        out[2 * Bn * Kk + b * Kk + j] = (float)parenti;
    }
}

// ---------------------------------------------------------------------------
extern "C" void kernel_launch(void* const* d_in, const int* in_sizes, int n_in,
                              void* d_out, int out_size) {
    const float* sampled = (const float*)d_in[0];  // [B, N, V] fp32
    const float* parent  = (const float*)d_in[1];  // [B, N]    fp32
    float* out = (float*)d_out;                    // 3 * B * K float32

    (void)in_sizes; (void)n_in; (void)out_size;

    kprep<<<Bn, 32>>>(parent);
    dim3 g(16, Bn * Nn);
    kpass1<<<g, 256>>>(sampled, parent);
    kfallback<<<Bn, 256>>>(sampled, parent);
    kselect<<<Bn, 256>>>(out);
}

// round 5
// speedup vs baseline: 4.7961x; 1.2080x over previous
#include <cuda_runtime.h>
#include <cstdint>

// Fixed shapes from reference setup_inputs
#define Bn 8
#define Nn 64
#define Vn 128000
#define Kk 64
#define CAP 16384
#define ROW_F4 32000          // float4 per (b,n) row (V/4)
#define TARGET 512.0f         // expected speculative candidate count per batch
#define SORTMAX 2048          // bitonic-sort capacity (pow2)

// Static device scratch (no allocations allowed)
__device__ float g_cutf[Bn];            // per-batch cut in product domain
__device__ float g_cutdiv[Bn * Nn];     // per-(b,n) conservative cut in v domain
__device__ unsigned g_cnt[Bn];
__device__ unsigned long long g_cand[Bn][CAP];

// ---------------------------------------------------------------------------
// Kernel 1: per-batch adaptive cut by warp-parallel bisection on
//   V * sum_n max(0, 1 - z/p_n) = TARGET.  Also zeros per-batch state.
// Rows with p_n <= cutf get cutdiv >= 1  ->  provably no candidates
// (v < 1 always), so kpass1 skips them without reading.
// ---------------------------------------------------------------------------
__global__ void kprep(const float* __restrict__ parent) {
    const int b = blockIdx.x;
    const int l = threadIdx.x;                 // 0..31, each owns 2 leaves
    float p0 = parent[b * Nn + l];
    float p1 = parent[b * Nn + 32 + l];
    float inv0 = 1.0f / p0;
    float inv1 = 1.0f / p1;

    float pm = fmaxf(p0, p1);
    #pragma unroll
    for (int o = 16; o; o >>= 1) pm = fmaxf(pm, __shfl_xor_sync(0xFFFFFFFFu, pm, o));

    float lo = 0.0f, hi = pm;
    for (int it = 0; it < 28; it++) {
        float mid = 0.5f * (lo + hi);
        float t = fmaxf(0.0f, 1.0f - mid * inv0) + fmaxf(0.0f, 1.0f - mid * inv1);
        #pragma unroll
        for (int o = 16; o; o >>= 1) t += __shfl_xor_sync(0xFFFFFFFFu, t, o);
        if (t * (float)Vn > TARGET) lo = mid; else hi = mid;
    }
    const float cutf = lo;
    if (l == 0) { g_cutf[b] = cutf; g_cnt[b] = 0; }
    const float SAFE = 0.999999f;   // covers fp rounding of the mul/div chain
    g_cutdiv[b * Nn + l]      = cutf * inv0 * SAFE;
    g_cutdiv[b * Nn + 32 + l] = cutf * inv1 * SAFE;
}

// ---------------------------------------------------------------------------
// Candidate push. key = bits<<32 | ~flat_idx : descending key order ==
// value desc, index asc == exact jax.lax.top_k tie-break.
// ---------------------------------------------------------------------------
__device__ __forceinline__ void push(int b, unsigned bits, unsigned idx) {
    unsigned pos = atomicAdd(&g_cnt[b], 1u);
    if (pos < CAP)
        g_cand[b][pos] = ((unsigned long long)bits << 32) |
                         (unsigned long long)(0xFFFFFFFFu - idx);
}

// ---------------------------------------------------------------------------
// Kernel 2: row-skipping collect. Grid (16, 512): 16 chunks per (b,n) row.
// Rows with cutdiv >= 1 exit without touching sampled[] (typ. ~61/64 rows).
// ---------------------------------------------------------------------------
__global__ __launch_bounds__(256) void kpass1(const float* __restrict__ sampled,
                                              const float* __restrict__ parent) {
    const int row = blockIdx.y;               // b*64 + n
    const float cutv = g_cutdiv[row];
    if (!(cutv < 1.0f)) return;               // skip row (also skips inf/nan)

    const int b = row >> 6;
    const float pp = parent[row];
    const float cutf = g_cutf[b];
    const float4* src = (const float4*)sampled + (size_t)row * ROW_F4;
    const unsigned colbase = (unsigned)(row & 63) * (unsigned)Vn;

    for (int i = blockIdx.x * 256 + threadIdx.x; i < ROW_F4; i += 16 * 256) {
        float4 x = src[i];
        float m = fmaxf(fmaxf(x.x, x.y), fmaxf(x.z, x.w));
        if (m >= cutv) {                      // rare
            unsigned c = colbase + 4u * (unsigned)i;
            float q0 = x.x * pp, q1 = x.y * pp, q2 = x.z * pp, q3 = x.w * pp;
            if (q0 >= cutf) push(b, __float_as_uint(q0), c + 0);
            if (q1 >= cutf) push(b, __float_as_uint(q1), c + 1);
            if (q2 >= cutf) push(b, __float_as_uint(q2), c + 2);
            if (q3 >= cutf) push(b, __float_as_uint(q3), c + 3);
        }
    }
}

// ---------------------------------------------------------------------------
// Kernel 3: exact fallback; self-guarded (no-op when speculation valid).
// Statistically never runs; correctness backstop only.
// ---------------------------------------------------------------------------
#define FBBINS 16384
__device__ unsigned g_fbhist[Bn][FBBINS];

__global__ void kfallback(const float* __restrict__ sampled,
                          const float* __restrict__ parent) {
    const int b = blockIdx.x;
    {
        unsigned c = g_cnt[b];
        if (c >= Kk && c <= CAP) return;       // speculation valid (uniform)
    }
    if (threadIdx.x == 0) g_cnt[b] = 0;
    for (int i = threadIdx.x; i < FBBINS; i += 256) g_fbhist[b][i] = 0;
    __syncthreads();

    const float* rowp = sampled + (size_t)b * Nn * Vn;
    const float* par = parent + b * Nn;
    for (int i = threadIdx.x; i < Nn * Vn; i += 256) {
        float p = rowp[i] * par[i / Vn];
        unsigned bin = __float_as_uint(p) >> 16;
        if (bin >= FBBINS) bin = FBBINS - 1;
        atomicAdd(&g_fbhist[b][bin], 1u);
    }
    __syncthreads();

    __shared__ unsigned s_th;
    if (threadIdx.x == 0) {
        unsigned cum = 0; unsigned t = 0;
        for (int bin = FBBINS - 1; bin >= 0; bin--) {
            cum += g_fbhist[b][bin];
            if (cum >= Kk) { t = (unsigned)bin; break; }
        }
        s_th = t << 16;
    }
    __syncthreads();
    const unsigned th = s_th;
    for (int i = threadIdx.x; i < Nn * Vn; i += 256) {
        float p = rowp[i] * par[i / Vn];
        unsigned bits = __float_as_uint(p);
        if (bits >= th) push(b, bits, (unsigned)i);
    }
}

// ---------------------------------------------------------------------------
// Kernel 4: per-batch top-K.
//  Fast path (cnt <= SORTMAX, the normal case): descending bitonic sort in
//  shared memory, emit first K. Pad key 0 < every real key (value bits > 0).
//  Slow path (cnt > SORTMAX, statistically never): repeated block argmax.
// Output: 1536 float32 = [token_ids B*K][topk_probs B*K][parents B*K]
// ---------------------------------------------------------------------------
__global__ __launch_bounds__(256) void kselect(float* __restrict__ out) {
    const int b = blockIdx.x;
    unsigned cnt = g_cnt[b];
    if (cnt > CAP) cnt = CAP;

    __shared__ unsigned long long buf[SORTMAX];
    __shared__ unsigned long long sel[Kk];

    if (cnt <= SORTMAX) {
        // size = next pow2 >= max(cnt, 64)
        unsigned size = 64;
        while (size < cnt) size <<= 1;

        for (unsigned i = threadIdx.x; i < size; i += 256)
            buf[i] = (i < cnt) ? g_cand[b][i] : 0ull;
        __syncthreads();

        // Bitonic sort, descending.
        for (unsigned k = 2; k <= size; k <<= 1) {
            for (unsigned j = k >> 1; j > 0; j >>= 1) {
                for (unsigned i = threadIdx.x; i < size; i += 256) {
                    unsigned ixj = i ^ j;
                    if (ixj > i) {
                        unsigned long long a = buf[i];
                        unsigned long long c = buf[ixj];
                        bool desc = ((i & k) == 0);
                        if (desc ? (a < c) : (a > c)) {
                            buf[i] = c;
                            buf[ixj] = a;
                        }
                    }
                }
                __syncthreads();
            }
        }
        if (threadIdx.x < Kk) sel[threadIdx.x] = buf[threadIdx.x];
        __syncthreads();
    } else {
        // Backstop: repeated argmax over global candidate array.
        __shared__ unsigned long long warpmax[8];
        unsigned long long* arr = g_cand[b];
        for (int j = 0; j < Kk; j++) {
            unsigned long long m = 0ull;
            int mpos = -1;
            for (unsigned i = threadIdx.x; i < cnt; i += 256) {
                unsigned long long v = arr[i];
                if (v > m) { m = v; mpos = (int)i; }
            }
            unsigned long long wm = m;
            #pragma unroll
            for (int o = 16; o; o >>= 1) {
                unsigned long long o2 = __shfl_down_sync(0xFFFFFFFFu, wm, o);
                if (o2 > wm) wm = o2;
            }
            if ((threadIdx.x & 31) == 0) warpmax[threadIdx.x >> 5] = wm;
            __syncthreads();
            if (threadIdx.x == 0) {
                unsigned long long g2 = warpmax[0];
                #pragma unroll
                for (int w = 1; w < 8; w++) if (warpmax[w] > g2) g2 = warpmax[w];
                warpmax[0] = g2;
                sel[j] = g2;
            }
            __syncthreads();
            unsigned long long gm = warpmax[0];
            if (mpos >= 0 && m == gm) arr[mpos] = 0ull;
            __syncthreads();
        }
    }

    if (threadIdx.x < Kk) {
        int j = threadIdx.x;
        unsigned long long key = sel[j];
        unsigned tok = 0, parenti = 0;
        float prob = 0.0f;
        if (key != 0ull) {
            unsigned idx = 0xFFFFFFFFu - (unsigned)(key & 0xFFFFFFFFull);
            parenti = idx / Vn;
            tok = idx - parenti * Vn;
            prob = __uint_as_float((unsigned)(key >> 32));
        }
        out[b * Kk + j]               = (float)tok;
        out[Bn * Kk + b * Kk + j]     = prob;
        out[2 * Bn * Kk + b * Kk + j] = (float)parenti;
    }
}

// ---------------------------------------------------------------------------
extern "C" void kernel_launch(void* const* d_in, const int* in_sizes, int n_in,
                              void* d_out, int out_size) {
    const float* sampled = (const float*)d_in[0];  // [B, N, V] fp32
    const float* parent  = (const float*)d_in[1];  // [B, N]    fp32
    float* out = (float*)d_out;                    // 3 * B * K float32

    (void)in_sizes; (void)n_in; (void)out_size;

    kprep<<<Bn, 32>>>(parent);
    dim3 g(16, Bn * Nn);
    kpass1<<<g, 256>>>(sampled, parent);
    kfallback<<<Bn, 256>>>(sampled, parent);
    kselect<<<Bn, 256>>>(out);
}

// round 6
// speedup vs baseline: 7.5402x; 1.5722x over previous
#include <cuda_runtime.h>
#include <cstdint>

// Fixed shapes from reference setup_inputs
#define Bn 8
#define Nn 64
#define Vn 128000
#define Kk 64
#define CAP 16384
#define ROW_F4 32000          // float4 per (b,n) row (V/4)
#define TARGET 384.0f         // expected speculative candidates per batch
#define SORTMAX 4096          // bitonic-sort capacity (pow2)
#define NCHUNK 32             // kpass1 chunks per batch

// Static device scratch (no allocations allowed)
__device__ float g_cutf[Bn];            // per-batch cut in product domain
__device__ float g_cutdiv[Bn * Nn];     // per-(b,n) conservative cut in v domain
__device__ unsigned g_cnt[Bn];
__device__ unsigned long long g_cand[Bn][CAP];

// ---------------------------------------------------------------------------
// Kernel 1: per-batch adaptive cut by warp-parallel bisection on
//   V * sum_n max(0, 1 - z/p_n) = TARGET.  Also zeros per-batch state.
// Rows with p_n <= cutf get cutdiv >= 1  ->  provably no candidates
// (v < 1 always), so kpass1 skips them without reading.
// ---------------------------------------------------------------------------
__global__ void kprep(const float* __restrict__ parent) {
    const int b = blockIdx.x;
    const int l = threadIdx.x;                 // 0..31, each owns 2 leaves
    float p0 = parent[b * Nn + l];
    float p1 = parent[b * Nn + 32 + l];
    float inv0 = 1.0f / p0;
    float inv1 = 1.0f / p1;

    float pm = fmaxf(p0, p1);
    #pragma unroll
    for (int o = 16; o; o >>= 1) pm = fmaxf(pm, __shfl_xor_sync(0xFFFFFFFFu, pm, o));

    float lo = 0.0f, hi = pm;
    for (int it = 0; it < 28; it++) {
        float mid = 0.5f * (lo + hi);
        float t = fmaxf(0.0f, 1.0f - mid * inv0) + fmaxf(0.0f, 1.0f - mid * inv1);
        #pragma unroll
        for (int o = 16; o; o >>= 1) t += __shfl_xor_sync(0xFFFFFFFFu, t, o);
        if (t * (float)Vn > TARGET) lo = mid; else hi = mid;
    }
    const float cutf = lo;
    if (l == 0) { g_cutf[b] = cutf; g_cnt[b] = 0; }
    const float SAFE = 0.999999f;   // covers fp rounding of the mul/div chain
    g_cutdiv[b * Nn + l]      = cutf * inv0 * SAFE;
    g_cutdiv[b * Nn + 32 + l] = cutf * inv1 * SAFE;
}

// ---------------------------------------------------------------------------
// Candidate push. key = bits<<32 | ~flat_idx : descending key order ==
// value desc, index asc == exact jax.lax.top_k tie-break.
// ---------------------------------------------------------------------------
__device__ __forceinline__ void push(int b, unsigned bits, unsigned idx) {
    unsigned pos = atomicAdd(&g_cnt[b], 1u);
    if (pos < CAP)
        g_cand[b][pos] = ((unsigned long long)bits << 32) |
                         (unsigned long long)(0xFFFFFFFFu - idx);
}

// ---------------------------------------------------------------------------
// Kernel 2: row-skipping collect. Grid (NCHUNK, Bn) = 256 blocks.
// Each block owns one vocab chunk of one batch and loops over the 64 rows,
// reading only active rows (cutdiv < 1; typically ~3 of 64).
// ---------------------------------------------------------------------------
#define CHUNK_F4 (ROW_F4 / NCHUNK)      // 1000 float4 per chunk
__global__ __launch_bounds__(256) void kpass1(const float* __restrict__ sampled,
                                              const float* __restrict__ parent) {
    const int b = blockIdx.y;
    const int base = blockIdx.x * CHUNK_F4;
    const float cutf = g_cutf[b];

    for (int n = 0; n < Nn; n++) {
        const float cutv = g_cutdiv[b * Nn + n];
        if (!(cutv < 1.0f)) continue;          // row provably empty: skip read

        const float pp = parent[b * Nn + n];
        const float4* src = (const float4*)sampled +
                            ((size_t)(b * Nn + n)) * ROW_F4 + base;
        const unsigned colbase = (unsigned)n * (unsigned)Vn + 4u * (unsigned)base;

        // 1000 float4 per block, 256 threads: 3 full quads + remainder handled
        // by bounds checks. Manual x4 unroll for MLP.
        for (int i = threadIdx.x; i < CHUNK_F4; i += 256 * 2) {
            int i1 = i + 256;
            float4 x0 = src[i];
            float4 x1 = (i1 < CHUNK_F4) ? src[i1] : make_float4(0.f,0.f,0.f,0.f);
            float m0 = fmaxf(fmaxf(x0.x, x0.y), fmaxf(x0.z, x0.w));
            float m1 = fmaxf(fmaxf(x1.x, x1.y), fmaxf(x1.z, x1.w));
            if (fmaxf(m0, m1) >= cutv) {       // rare
                unsigned c0 = colbase + 4u * (unsigned)i;
                float q0 = x0.x * pp, q1 = x0.y * pp, q2 = x0.z * pp, q3 = x0.w * pp;
                if (q0 >= cutf) push(b, __float_as_uint(q0), c0 + 0);
                if (q1 >= cutf) push(b, __float_as_uint(q1), c0 + 1);
                if (q2 >= cutf) push(b, __float_as_uint(q2), c0 + 2);
                if (q3 >= cutf) push(b, __float_as_uint(q3), c0 + 3);
                unsigned c1 = colbase + 4u * (unsigned)i1;
                float r0 = x1.x * pp, r1 = x1.y * pp, r2 = x1.z * pp, r3 = x1.w * pp;
                if (r0 >= cutf) push(b, __float_as_uint(r0), c1 + 0);
                if (r1 >= cutf) push(b, __float_as_uint(r1), c1 + 1);
                if (r2 >= cutf) push(b, __float_as_uint(r2), c1 + 2);
                if (r3 >= cutf) push(b, __float_as_uint(r3), c1 + 3);
            }
        }
    }
}

// ---------------------------------------------------------------------------
// Kernel 3 (fused): validate -> (fallback if needed) -> top-K -> output.
// 8 blocks x 512 threads.
// Output: 1536 float32 = [token_ids B*K][topk_probs B*K][parents B*K]
// ---------------------------------------------------------------------------
#define FBBINS 16384
__device__ unsigned g_fbhist[Bn][FBBINS];
#define STH 512

__global__ __launch_bounds__(STH) void kselect(float* __restrict__ out,
                                               const float* __restrict__ sampled,
                                               const float* __restrict__ parent) {
    const int b = blockIdx.x;
    unsigned cnt = g_cnt[b];

    // ---- fallback: exact histogram re-pass (statistically never taken) ----
    if (cnt < Kk || cnt > CAP) {
        if (threadIdx.x == 0) g_cnt[b] = 0;
        for (int i = threadIdx.x; i < FBBINS; i += STH) g_fbhist[b][i] = 0;
        __syncthreads();
        const float* rowp = sampled + (size_t)b * Nn * Vn;
        const float* par = parent + b * Nn;
        for (int i = threadIdx.x; i < Nn * Vn; i += STH) {
            float p = rowp[i] * par[i / Vn];
            unsigned bin = __float_as_uint(p) >> 16;
            if (bin >= FBBINS) bin = FBBINS - 1;
            atomicAdd(&g_fbhist[b][bin], 1u);
        }
        __syncthreads();
        __shared__ unsigned s_th;
        if (threadIdx.x == 0) {
            unsigned cum = 0; unsigned t = 0;
            for (int bin = FBBINS - 1; bin >= 0; bin--) {
                cum += g_fbhist[b][bin];
                if (cum >= Kk) { t = (unsigned)bin; break; }
            }
            s_th = t << 16;
        }
        __syncthreads();
        const unsigned th = s_th;
        for (int i = threadIdx.x; i < Nn * Vn; i += STH) {
            float p = rowp[i] * par[i / Vn];
            unsigned bits = __float_as_uint(p);
            if (bits >= th) push(b, bits, (unsigned)i);
        }
        __syncthreads();
        cnt = g_cnt[b];
        if (cnt > CAP) cnt = CAP;
    }

    __shared__ unsigned long long buf[SORTMAX];
    __shared__ unsigned long long sel[Kk];

    if (cnt <= SORTMAX) {
        unsigned size = 64;
        while (size < cnt) size <<= 1;
        for (unsigned i = threadIdx.x; i < size; i += STH)
            buf[i] = (i < cnt) ? g_cand[b][i] : 0ull;
        __syncthreads();
        // Bitonic sort, descending (pad key 0 < any real key).
        for (unsigned k = 2; k <= size; k <<= 1) {
            for (unsigned j = k >> 1; j > 0; j >>= 1) {
                for (unsigned i = threadIdx.x; i < size; i += STH) {
                    unsigned ixj = i ^ j;
                    if (ixj > i) {
                        unsigned long long a = buf[i];
                        unsigned long long c = buf[ixj];
                        bool desc = ((i & k) == 0);
                        if (desc ? (a < c) : (a > c)) { buf[i] = c; buf[ixj] = a; }
                    }
                }
                __syncthreads();
            }
        }
        if (threadIdx.x < Kk) sel[threadIdx.x] = buf[threadIdx.x];
        __syncthreads();
    } else {
        // Backstop: repeated argmax over global candidate array.
        __shared__ unsigned long long warpmax[STH / 32];
        unsigned long long* arr = g_cand[b];
        for (int j = 0; j < Kk; j++) {
            unsigned long long m = 0ull;
            int mpos = -1;
            for (unsigned i = threadIdx.x; i < cnt; i += STH) {
                unsigned long long v = arr[i];
                if (v > m) { m = v; mpos = (int)i; }
            }
            unsigned long long wm = m;
            #pragma unroll
            for (int o = 16; o; o >>= 1) {
                unsigned long long o2 = __shfl_down_sync(0xFFFFFFFFu, wm, o);
                if (o2 > wm) wm = o2;
            }
            if ((threadIdx.x & 31) == 0) warpmax[threadIdx.x >> 5] = wm;
            __syncthreads();
            if (threadIdx.x == 0) {
                unsigned long long g2 = warpmax[0];
                #pragma unroll
                for (int w = 1; w < STH / 32; w++) if (warpmax[w] > g2) g2 = warpmax[w];
                warpmax[0] = g2;
                sel[j] = g2;
            }
            __syncthreads();
            unsigned long long gm = warpmax[0];
            if (mpos >= 0 && m == gm) arr[mpos] = 0ull;
            __syncthreads();
        }
    }

    if (threadIdx.x < Kk) {
        int j = threadIdx.x;
        unsigned long long key = sel[j];
        unsigned tok = 0, parenti = 0;
        float prob = 0.0f;
        if (key != 0ull) {
            unsigned idx = 0xFFFFFFFFu - (unsigned)(key & 0xFFFFFFFFull);
            parenti = idx / Vn;
            tok = idx - parenti * Vn;
            prob = __uint_as_float((unsigned)(key >> 32));
        }
        out[b * Kk + j]               = (float)tok;
        out[Bn * Kk + b * Kk + j]     = prob;
        out[2 * Bn * Kk + b * Kk + j] = (float)parenti;
    }
}

// ---------------------------------------------------------------------------
extern "C" void kernel_launch(void* const* d_in, const int* in_sizes, int n_in,
                              void* d_out, int out_size) {
    const float* sampled = (const float*)d_in[0];  // [B, N, V] fp32
    const float* parent  = (const float*)d_in[1];  // [B, N]    fp32
    float* out = (float*)d_out;                    // 3 * B * K float32

    (void)in_sizes; (void)n_in; (void)out_size;

    kprep<<<Bn, 32>>>(parent);
    dim3 g(NCHUNK, Bn);
    kpass1<<<g, 256>>>(sampled, parent);
    kselect<<<Bn, STH>>>(out, sampled, parent);
}

// round 7
// speedup vs baseline: 10.0068x; 1.3271x over previous
#include <cuda_runtime.h>
#include <cstdint>

// Fixed shapes from reference setup_inputs
#define Bn 8
#define Nn 64
#define Vn 128000
#define Kk 64
#define CAP 16384
#define ROW_F4 32000            // float4 per (b,n) row (V/4)
#define NCHUNK 32               // chunks (blocks) per batch
#define CHUNK_F4 (ROW_F4 / NCHUNK)   // 1000 float4 per chunk
#define SORTMAX 2048            // bitonic capacity (pow2)
#define FBBINS 16384
#define TPB 256

// Static device scratch (no device-side allocation allowed).
// All counters are left at 0 by the end of each launch (replay-safe).
__device__ unsigned g_cnt[Bn];
__device__ unsigned g_done[Bn];
__device__ unsigned long long g_cand[Bn][CAP];
__device__ unsigned g_fbhist[Bn][FBBINS];

// key = bits<<32 | ~flat_idx : descending key order == value desc, index asc
// == exact jax.lax.top_k tie-break. All real keys > 0 (value bits > 0).
__device__ __forceinline__ void push(int b, unsigned bits, unsigned idx) {
    unsigned pos = atomicAdd(&g_cnt[b], 1u);
    if (pos < CAP)
        g_cand[b][pos] = ((unsigned long long)bits << 32) |
                         (unsigned long long)(0xFFFFFFFFu - idx);
}

// ---------------------------------------------------------------------------
// Single fused kernel. Grid (NCHUNK, Bn) x 256 threads.
// Phase A (all blocks): analytic cut, row-skipping candidate collect.
// Phase B (last block per batch): validate -> (exact fallback) -> bitonic
// top-K -> write output -> reset counters.
// ---------------------------------------------------------------------------
__global__ __launch_bounds__(TPB) void keagle(float* __restrict__ out,
                                              const float* __restrict__ sampled,
                                              const float* __restrict__ parent) {
    const int b = blockIdx.y;
    __shared__ float s_par[Nn];
    __shared__ float s_cutf;

    // --- cut: cutf = pmax * (1 - 128/V). Top row alone yields ~128 expected
    // candidates (Binomial(V,128/V): P(<64) ~ 1e-8, backstopped); all-equal
    // parents cap expectation at 64*128 = 8192 < CAP.
    if (threadIdx.x < Nn) s_par[threadIdx.x] = parent[b * Nn + threadIdx.x];
    __syncthreads();
    if (threadIdx.x < 32) {
        float pm = fmaxf(s_par[threadIdx.x], s_par[threadIdx.x + 32]);
        #pragma unroll
        for (int o = 16; o; o >>= 1)
            pm = fmaxf(pm, __shfl_xor_sync(0xFFFFFFFFu, pm, o));
        if (threadIdx.x == 0) s_cutf = pm * (1.0f - 128.0f / (float)Vn);
    }
    __syncthreads();
    const float cutf = s_cutf;

    // --- Phase A: collect over active rows of this chunk.
    const int base = blockIdx.x * CHUNK_F4;
    for (int n = 0; n < Nn; n++) {
        const float pp = s_par[n];
        if (pp < cutf) continue;      // safe: v<1 => RN(v*pp) <= pp < cutf

        const float4* src = (const float4*)sampled +
                            ((size_t)(b * Nn + n)) * ROW_F4 + base;
        const unsigned colbase = (unsigned)n * (unsigned)Vn + 4u * (unsigned)base;

        for (int i = threadIdx.x; i < CHUNK_F4; i += TPB * 2) {
            int i1 = i + TPB;
            float4 x0 = src[i];
            float4 x1 = (i1 < CHUNK_F4) ? src[i1] : make_float4(0.f,0.f,0.f,0.f);
            float m0 = fmaxf(fmaxf(x0.x, x0.y), fmaxf(x0.z, x0.w));
            float m1 = fmaxf(fmaxf(x1.x, x1.y), fmaxf(x1.z, x1.w));
            // Exact screen: RN monotone => group has a candidate iff max does.
            if (fmaxf(m0, m1) * pp >= cutf) {        // rare
                unsigned c0 = colbase + 4u * (unsigned)i;
                float q0 = x0.x*pp, q1 = x0.y*pp, q2 = x0.z*pp, q3 = x0.w*pp;
                if (q0 >= cutf) push(b, __float_as_uint(q0), c0 + 0);
                if (q1 >= cutf) push(b, __float_as_uint(q1), c0 + 1);
                if (q2 >= cutf) push(b, __float_as_uint(q2), c0 + 2);
                if (q3 >= cutf) push(b, __float_as_uint(q3), c0 + 3);
                unsigned c1 = colbase + 4u * (unsigned)i1;
                float r0 = x1.x*pp, r1 = x1.y*pp, r2 = x1.z*pp, r3 = x1.w*pp;
                if (r0 >= cutf) push(b, __float_as_uint(r0), c1 + 0);
                if (r1 >= cutf) push(b, __float_as_uint(r1), c1 + 1);
                if (r2 >= cutf) push(b, __float_as_uint(r2), c1 + 2);
                if (r3 >= cutf) push(b, __float_as_uint(r3), c1 + 3);
            }
        }
    }

    // --- handoff: last block of this batch does selection.
    __threadfence();
    __shared__ unsigned s_rank;
    __syncthreads();
    if (threadIdx.x == 0) s_rank = atomicAdd(&g_done[b], 1u);
    __syncthreads();
    if (s_rank != NCHUNK - 1) return;
    __threadfence();

    unsigned cnt = atomicAdd(&g_cnt[b], 0u);

    // --- exact fallback (statistically never; correctness backstop).
    if (cnt < Kk || cnt > CAP) {
        if (threadIdx.x == 0) g_cnt[b] = 0;
        for (int i = threadIdx.x; i < FBBINS; i += TPB) g_fbhist[b][i] = 0;
        __syncthreads();
        const float* rowp = sampled + (size_t)b * Nn * Vn;
        for (int i = threadIdx.x; i < Nn * Vn; i += TPB) {
            float p = rowp[i] * s_par[i / Vn];
            unsigned bin = __float_as_uint(p) >> 16;
            if (bin >= FBBINS) bin = FBBINS - 1;
            atomicAdd(&g_fbhist[b][bin], 1u);
        }
        __syncthreads();
        __shared__ unsigned s_th;
        if (threadIdx.x == 0) {
            unsigned cum = 0; unsigned t = 0;
            for (int bin = FBBINS - 1; bin >= 0; bin--) {
                cum += g_fbhist[b][bin];
                if (cum >= Kk) { t = (unsigned)bin; break; }
            }
            s_th = t << 16;
        }
        __syncthreads();
        const unsigned th = s_th;
        for (int i = threadIdx.x; i < Nn * Vn; i += TPB) {
            float p = rowp[i] * s_par[i / Vn];
            unsigned bits = __float_as_uint(p);
            if (bits >= th) push(b, bits, (unsigned)i);
        }
        __syncthreads();
        cnt = atomicAdd(&g_cnt[b], 0u);
        if (cnt > CAP) cnt = CAP;
    }

    // --- top-K selection.
    __shared__ unsigned long long buf[SORTMAX];
    __shared__ unsigned long long sel[Kk];
    volatile unsigned long long* cand = g_cand[b];   // cross-SM coherence

    if (cnt <= SORTMAX) {
        unsigned size = 64;
        while (size < cnt) size <<= 1;
        for (unsigned i = threadIdx.x; i < size; i += TPB)
            buf[i] = (i < cnt) ? cand[i] : 0ull;
        __syncthreads();
        for (unsigned k = 2; k <= size; k <<= 1) {
            for (unsigned j = k >> 1; j > 0; j >>= 1) {
                for (unsigned i = threadIdx.x; i < size; i += TPB) {
                    unsigned ixj = i ^ j;
                    if (ixj > i) {
                        unsigned long long a = buf[i];
                        unsigned long long c = buf[ixj];
                        bool desc = ((i & k) == 0);
                        if (desc ? (a < c) : (a > c)) { buf[i] = c; buf[ixj] = a; }
                    }
                }
                __syncthreads();
            }
        }
        if (threadIdx.x < Kk) sel[threadIdx.x] = buf[threadIdx.x];
        __syncthreads();
    } else {
        // Backstop: repeated argmax over the global candidate array.
        __shared__ unsigned long long warpmax[TPB / 32];
        for (int j = 0; j < Kk; j++) {
            unsigned long long m = 0ull;
            int mpos = -1;
            for (unsigned i = threadIdx.x; i < cnt; i += TPB) {
                unsigned long long v = cand[i];
                if (v > m) { m = v; mpos = (int)i; }
            }
            unsigned long long wm = m;
            #pragma unroll
            for (int o = 16; o; o >>= 1) {
                unsigned long long o2 = __shfl_down_sync(0xFFFFFFFFu, wm, o);
                if (o2 > wm) wm = o2;
            }
            if ((threadIdx.x & 31) == 0) warpmax[threadIdx.x >> 5] = wm;
            __syncthreads();
            if (threadIdx.x == 0) {
                unsigned long long g2 = warpmax[0];
                #pragma unroll
                for (int w = 1; w < TPB / 32; w++) if (warpmax[w] > g2) g2 = warpmax[w];
                warpmax[0] = g2;
                sel[j] = g2;
            }
            __syncthreads();
            unsigned long long gm = warpmax[0];
            if (mpos >= 0 && m == gm) g_cand[b][mpos] = 0ull;
            __syncthreads();
        }
    }

    // --- output: 1536 f32 = [token_ids B*K][topk_probs B*K][parents B*K]
    if (threadIdx.x < Kk) {
        int j = threadIdx.x;
        unsigned long long key = sel[j];
        unsigned tok = 0, parenti = 0;
        float prob = 0.0f;
        if (key != 0ull) {
            unsigned idx = 0xFFFFFFFFu - (unsigned)(key & 0xFFFFFFFFull);
            parenti = idx / Vn;
            tok = idx - parenti * Vn;
            prob = __uint_as_float((unsigned)(key >> 32));
        }
        out[b * Kk + j]               = (float)tok;
        out[Bn * Kk + b * Kk + j]     = prob;
        out[2 * Bn * Kk + b * Kk + j] = (float)parenti;
    }

    // --- reset for next graph replay (deterministic launch-to-launch state).
    if (threadIdx.x == 0) { g_cnt[b] = 0; g_done[b] = 0; }
}

// ---------------------------------------------------------------------------
extern "C" void kernel_launch(void* const* d_in, const int* in_sizes, int n_in,
                              void* d_out, int out_size) {
    const float* sampled = (const float*)d_in[0];  // [B, N, V] fp32
    const float* parent  = (const float*)d_in[1];  // [B, N]    fp32
    float* out = (float*)d_out;                    // 3 * B * K float32

    (void)in_sizes; (void)n_in; (void)out_size;

    dim3 g(NCHUNK, Bn);
    keagle<<<g, TPB>>>(out, sampled, parent);
}

// round 8
// speedup vs baseline: 11.1818x; 1.1174x over previous
#include <cuda_runtime.h>
#include <cstdint>

// Fixed shapes from reference setup_inputs
#define Bn 8
#define Nn 64
#define Vn 128000
#define Kk 64
#define CAP 16384
#define ROW_F4 32000            // float4 per (b,n) row (V/4)
#define SCAP 2048               // shared candidate capacity (pow2)
#define FBBINS 16384
#define TPB 1024

// Global scratch only for the (statistically never taken) exact fallback.
__device__ unsigned g_cnt[Bn];
__device__ unsigned long long g_cand[Bn][CAP];
__device__ unsigned g_fbhist[Bn][FBBINS];

__device__ __forceinline__ unsigned long long mkkey(unsigned bits, unsigned idx) {
    // key = bits<<32 | ~idx : desc key order == value desc, index asc
    // == exact jax.lax.top_k tie-break. Real keys > 0 (value bits > 0).
    return ((unsigned long long)bits << 32) |
           (unsigned long long)(0xFFFFFFFFu - idx);
}

__device__ __forceinline__ void gpush(int b, unsigned bits, unsigned idx) {
    unsigned pos = atomicAdd(&g_cnt[b], 1u);
    if (pos < CAP) g_cand[b][pos] = mkkey(bits, idx);
}

// ---------------------------------------------------------------------------
// Single fused kernel: one block per batch, 1024 threads.
//   1. analytic cut: cutf = pmax*(1 - 128/V)  (expected ~128 candidates)
//   2. compact active-row list (rows with pp >= cutf; v<1 => others empty)
//   3. stream active rows, screen 16 elems per compare, push to SHARED
//   4. in-place shared bitonic top-K (or exact global fallback) -> output
// ---------------------------------------------------------------------------
__global__ __launch_bounds__(TPB) void keagle(float* __restrict__ out,
                                              const float* __restrict__ sampled,
                                              const float* __restrict__ parent) {
    const int b = blockIdx.x;
    const int tid = threadIdx.x;

    __shared__ float s_par[Nn];
    __shared__ float s_cut;
    __shared__ unsigned s_cnt, s_na;
    __shared__ unsigned char s_rows[Nn];
    __shared__ unsigned long long s_cand[SCAP];
    __shared__ unsigned long long s_sel[Kk];

    if (tid == 0) { s_cnt = 0; s_na = 0; }
    if (tid < Nn) s_par[tid] = parent[b * Nn + tid];
    __syncthreads();

    if (tid < 32) {
        float pm = fmaxf(s_par[tid], s_par[tid + 32]);
        #pragma unroll
        for (int o = 16; o; o >>= 1)
            pm = fmaxf(pm, __shfl_xor_sync(0xFFFFFFFFu, pm, o));
        if (tid == 0) s_cut = pm * (1.0f - 128.0f / (float)Vn);
    }
    __syncthreads();
    const float cutf = s_cut;

    // Active-row list (row empty unless pp >= cutf: v<1 => RN(v*pp) <= pp).
    if (tid < Nn && s_par[tid] >= cutf) {
        unsigned r = atomicAdd(&s_na, 1u);
        s_rows[r] = (unsigned char)tid;
    }
    __syncthreads();
    const unsigned na = s_na;

    // Stream active rows (typically 1). 4-way unrolled strided loads for MLP.
    for (unsigned a = 0; a < na; a++) {
        const int n = s_rows[a];
        const float pp = s_par[n];
        const float4* src = (const float4*)sampled +
                            ((size_t)(b * Nn + n)) * ROW_F4;
        const unsigned colbase = (unsigned)n * (unsigned)Vn;
        const float4 z = make_float4(0.f, 0.f, 0.f, 0.f);

        #pragma unroll 1
        for (int k = 0; k < 8; k++) {
            int i0 = tid + k * 4096;
            int i1 = i0 + 1024, i2 = i0 + 2048, i3 = i0 + 3072;
            float4 x0 = (i0 < ROW_F4) ? src[i0] : z;
            float4 x1 = (i1 < ROW_F4) ? src[i1] : z;
            float4 x2 = (i2 < ROW_F4) ? src[i2] : z;
            float4 x3 = (i3 < ROW_F4) ? src[i3] : z;
            float m0 = fmaxf(fmaxf(x0.x, x0.y), fmaxf(x0.z, x0.w));
            float m1 = fmaxf(fmaxf(x1.x, x1.y), fmaxf(x1.z, x1.w));
            float m2 = fmaxf(fmaxf(x2.x, x2.y), fmaxf(x2.z, x2.w));
            float m3 = fmaxf(fmaxf(x3.x, x3.y), fmaxf(x3.z, x3.w));
            float m = fmaxf(fmaxf(m0, m1), fmaxf(m2, m3));
            // Exact: RN monotone => some element passes iff max passes.
            if (m * pp >= cutf) {                     // rare (~1 warp-hit/row)
                const float4 xs[4] = {x0, x1, x2, x3};
                const int is[4] = {i0, i1, i2, i3};
                #pragma unroll
                for (int u = 0; u < 4; u++) {
                    float q0 = xs[u].x * pp, q1 = xs[u].y * pp;
                    float q2 = xs[u].z * pp, q3 = xs[u].w * pp;
                    unsigned c = colbase + 4u * (unsigned)is[u];
                    if (q0 >= cutf) { unsigned p_ = atomicAdd(&s_cnt, 1u); if (p_ < SCAP) s_cand[p_] = mkkey(__float_as_uint(q0), c + 0); }
                    if (q1 >= cutf) { unsigned p_ = atomicAdd(&s_cnt, 1u); if (p_ < SCAP) s_cand[p_] = mkkey(__float_as_uint(q1), c + 1); }
                    if (q2 >= cutf) { unsigned p_ = atomicAdd(&s_cnt, 1u); if (p_ < SCAP) s_cand[p_] = mkkey(__float_as_uint(q2), c + 2); }
                    if (q3 >= cutf) { unsigned p_ = atomicAdd(&s_cnt, 1u); if (p_ < SCAP) s_cand[p_] = mkkey(__float_as_uint(q3), c + 3); }
                }
            }
        }
    }
    __syncthreads();
    unsigned cnt = s_cnt;
    const bool fb = (cnt < Kk || cnt > SCAP);

    if (!fb) {
        // ---- fast path: in-place shared bitonic sort, descending ----
        unsigned size = 64;
        while (size < cnt) size <<= 1;
        for (unsigned i = cnt + tid; i < size; i += TPB) s_cand[i] = 0ull;
        __syncthreads();
        for (unsigned k = 2; k <= size; k <<= 1) {
            for (unsigned j = k >> 1; j > 0; j >>= 1) {
                for (unsigned i = tid; i < size; i += TPB) {
                    unsigned ixj = i ^ j;
                    if (ixj > i) {
                        unsigned long long a = s_cand[i];
                        unsigned long long c = s_cand[ixj];
                        bool desc = ((i & k) == 0);
                        if (desc ? (a < c) : (a > c)) {
                            s_cand[i] = c; s_cand[ixj] = a;
                        }
                    }
                }
                __syncthreads();
            }
        }
        if (tid < Kk) s_sel[tid] = s_cand[tid];
        __syncthreads();
    } else {
        // ---- exact fallback (correctness backstop; never taken in practice)
        if (tid == 0) g_cnt[b] = 0;
        for (int i = tid; i < FBBINS; i += TPB) g_fbhist[b][i] = 0;
        __syncthreads();
        const float* rowp = sampled + (size_t)b * Nn * Vn;
        for (int i = tid; i < Nn * Vn; i += TPB) {
            float p = rowp[i] * s_par[i / Vn];
            unsigned bin = __float_as_uint(p) >> 16;
            if (bin >= FBBINS) bin = FBBINS - 1;
            atomicAdd(&g_fbhist[b][bin], 1u);
        }
        __syncthreads();
        __shared__ unsigned s_th;
        if (tid == 0) {
            unsigned cum = 0; unsigned t = 0;
            for (int bin = FBBINS - 1; bin >= 0; bin--) {
                cum += g_fbhist[b][bin];
                if (cum >= Kk) { t = (unsigned)bin; break; }
            }
            s_th = t << 16;
        }
        __syncthreads();
        const unsigned th = s_th;
        for (int i = tid; i < Nn * Vn; i += TPB) {
            float p = rowp[i] * s_par[i / Vn];
            unsigned bits = __float_as_uint(p);
            if (bits >= th) gpush(b, bits, (unsigned)i);
        }
        __syncthreads();
        cnt = g_cnt[b];
        if (cnt > CAP) cnt = CAP;

        // Repeated block argmax over global candidates (handles any cnt).
        __shared__ unsigned long long warpmax[TPB / 32];
        for (int j = 0; j < Kk; j++) {
            unsigned long long m = 0ull;
            int mpos = -1;
            for (unsigned i = tid; i < cnt; i += TPB) {
                unsigned long long v = g_cand[b][i];
                if (v > m) { m = v; mpos = (int)i; }
            }
            unsigned long long wm = m;
            #pragma unroll
            for (int o = 16; o; o >>= 1) {
                unsigned long long o2 = __shfl_down_sync(0xFFFFFFFFu, wm, o);
                if (o2 > wm) wm = o2;
            }
            if ((tid & 31) == 0) warpmax[tid >> 5] = wm;
            __syncthreads();
            if (tid == 0) {
                unsigned long long g2 = warpmax[0];
                #pragma unroll
                for (int w = 1; w < TPB / 32; w++)
                    if (warpmax[w] > g2) g2 = warpmax[w];
                warpmax[0] = g2;
                s_sel[j] = g2;
            }
            __syncthreads();
            unsigned long long gm = warpmax[0];
            if (mpos >= 0 && m == gm) g_cand[b][mpos] = 0ull;
            __syncthreads();
        }
    }

    // ---- output: 1536 f32 = [token_ids B*K][topk_probs B*K][parents B*K]
    if (tid < Kk) {
        unsigned long long key = s_sel[tid];
        unsigned tok = 0, parenti = 0;
        float prob = 0.0f;
        if (key != 0ull) {
            unsigned idx = 0xFFFFFFFFu - (unsigned)(key & 0xFFFFFFFFull);
            parenti = idx / Vn;
            tok = idx - parenti * Vn;
            prob = __uint_as_float((unsigned)(key >> 32));
        }
        out[b * Kk + tid]               = (float)tok;
        out[Bn * Kk + b * Kk + tid]     = prob;
        out[2 * Bn * Kk + b * Kk + tid] = (float)parenti;
    }
}

// ---------------------------------------------------------------------------
extern "C" void kernel_launch(void* const* d_in, const int* in_sizes, int n_in,
                              void* d_out, int out_size) {
    const float* sampled = (const float*)d_in[0];  // [B, N, V] fp32
    const float* parent  = (const float*)d_in[1];  // [B, N]    fp32
    float* out = (float*)d_out;                    // 3 * B * K float32

    (void)in_sizes; (void)n_in; (void)out_size;

    keagle<<<Bn, TPB>>>(out, sampled, parent);
}

// round 9
// speedup vs baseline: 14.7600x; 1.3200x over previous
#include <cuda_runtime.h>
#include <cstdint>

// Fixed shapes from reference setup_inputs
#define Bn 8
#define Nn 64
#define Vn 128000
#define Kk 64
#define CAP 16384
#define ROW_F4 32000                 // float4 per (b,n) row (V/4)
#define CH 16                        // chunks (blocks) per batch
#define CHUNK_F4 (ROW_F4 / CH)       // 2000 float4 per chunk
#define RANKMAX 512                  // rank-select ceiling (never exceeded)
#define FBBINS 16384
#define TPB 256

// Device scratch (no allocation allowed). Counters reset at end of launch.
__device__ unsigned g_cnt[Bn];
__device__ unsigned g_done[Bn];
__device__ unsigned long long g_cand[Bn][CAP];
__device__ unsigned g_fbhist[Bn][FBBINS];

__device__ __forceinline__ unsigned long long mkkey(unsigned bits, unsigned idx) {
    // key = bits<<32 | ~idx : desc key order == value desc, index asc
    // == exact jax.lax.top_k tie-break. Real keys > 0 (value bits > 0).
    return ((unsigned long long)bits << 32) |
           (unsigned long long)(0xFFFFFFFFu - idx);
}

__device__ __forceinline__ void gpush(int b, unsigned bits, unsigned idx) {
    unsigned pos = atomicAdd(&g_cnt[b], 1u);
    if (pos < CAP) g_cand[b][pos] = mkkey(bits, idx);
}

// ---------------------------------------------------------------------------
// Single fused kernel. Grid (CH, Bn) = 128 blocks x 256 threads.
// Phase A (all blocks): analytic cut, stream own chunk of active rows,
//   push candidates to global.
// Phase B (last block per batch): validate -> rank-select top-K (or exact
//   fallback) -> write output -> reset counters.
// ---------------------------------------------------------------------------
__global__ __launch_bounds__(TPB) void keagle(float* __restrict__ out,
                                              const float* __restrict__ sampled,
                                              const float* __restrict__ parent) {
    const int b = blockIdx.y;
    const int tid = threadIdx.x;

    __shared__ float s_par[Nn];
    __shared__ float s_cut;
    __shared__ unsigned s_na, s_rank;
    __shared__ unsigned char s_rows[Nn];

    if (tid == 0) s_na = 0;
    if (tid < Nn) s_par[tid] = parent[b * Nn + tid];
    __syncthreads();

    // cutf = pmax * (1 - 128/V): expected ~128 candidates from the top row
    // (Binomial(V,128/V), P(<64) ~ 1e-8; exact fallback backstops).
    if (tid < 32) {
        float pm = fmaxf(s_par[tid], s_par[tid + 32]);
        #pragma unroll
        for (int o = 16; o; o >>= 1)
            pm = fmaxf(pm, __shfl_xor_sync(0xFFFFFFFFu, pm, o));
        if (tid == 0) s_cut = pm * (1.0f - 128.0f / (float)Vn);
    }
    __syncthreads();
    const float cutf = s_cut;

    // Active rows: pp >= cutf (v<1 => RN(v*pp) <= pp < cutf for others).
    if (tid < Nn && s_par[tid] >= cutf) {
        unsigned r = atomicAdd(&s_na, 1u);
        s_rows[r] = (unsigned char)tid;
    }
    __syncthreads();
    const unsigned na = s_na;
    const int base = blockIdx.x * CHUNK_F4;

    // Phase A: stream own chunk of each active row (typically 1 row).
    for (unsigned a = 0; a < na; a++) {
        const int n = s_rows[a];
        const float pp = s_par[n];
        const float4* src = (const float4*)sampled +
                            ((size_t)(b * Nn + n)) * ROW_F4 + base;
        const unsigned colbase = (unsigned)n * (unsigned)Vn + 4u * (unsigned)base;
        const float4 z = make_float4(0.f, 0.f, 0.f, 0.f);

        #pragma unroll
        for (int k = 0; k < 2; k++) {
            int i0 = k * 1024 + tid;
            int i1 = i0 + 256, i2 = i0 + 512, i3 = i0 + 768;
            float4 x0 = (i0 < CHUNK_F4) ? src[i0] : z;
            float4 x1 = (i1 < CHUNK_F4) ? src[i1] : z;
            float4 x2 = (i2 < CHUNK_F4) ? src[i2] : z;
            float4 x3 = (i3 < CHUNK_F4) ? src[i3] : z;
            float m0 = fmaxf(fmaxf(x0.x, x0.y), fmaxf(x0.z, x0.w));
            float m1 = fmaxf(fmaxf(x1.x, x1.y), fmaxf(x1.z, x1.w));
            float m2 = fmaxf(fmaxf(x2.x, x2.y), fmaxf(x2.z, x2.w));
            float m3 = fmaxf(fmaxf(x3.x, x3.y), fmaxf(x3.z, x3.w));
            float m = fmaxf(fmaxf(m0, m1), fmaxf(m2, m3));
            // Exact screen: RN monotone => some elem passes iff max passes.
            if (m * pp >= cutf) {                       // rare
                const float4 xs[4] = {x0, x1, x2, x3};
                const int is[4] = {i0, i1, i2, i3};
                #pragma unroll
                for (int u = 0; u < 4; u++) {
                    float q0 = xs[u].x * pp, q1 = xs[u].y * pp;
                    float q2 = xs[u].z * pp, q3 = xs[u].w * pp;
                    unsigned c = colbase + 4u * (unsigned)is[u];
                    if (q0 >= cutf) gpush(b, __float_as_uint(q0), c + 0);
                    if (q1 >= cutf) gpush(b, __float_as_uint(q1), c + 1);
                    if (q2 >= cutf) gpush(b, __float_as_uint(q2), c + 2);
                    if (q3 >= cutf) gpush(b, __float_as_uint(q3), c + 3);
                }
            }
        }
    }

    // Handoff: last block of this batch performs selection.
    __threadfence();
    __syncthreads();
    if (tid == 0) s_rank = atomicAdd(&g_done[b], 1u);
    __syncthreads();
    if (s_rank != CH - 1) return;
    __threadfence();

    unsigned cnt = atomicAdd(&g_cnt[b], 0u);

    __shared__ unsigned long long s_cand[RANKMAX];
    __shared__ unsigned long long s_sel[Kk];

    if (cnt >= Kk && cnt <= RANKMAX) {
        // ---- fast path: rank selection (3 barriers total) ----
        for (unsigned i = tid; i < cnt; i += TPB)
            s_cand[i] = __ldcg(&g_cand[b][i]);
        __syncthreads();
        for (unsigned i = tid; i < cnt; i += TPB) {
            unsigned long long me = s_cand[i];
            int r = 0;
            for (unsigned j = 0; j < cnt; j++) r += (s_cand[j] > me);
            if (r < Kk) s_sel[r] = me;     // ranks unique (keys unique)
        }
        __syncthreads();
    } else {
        // ---- backstop paths (statistically never taken) ----
        if (cnt < Kk) {
            // exact histogram re-pass over the whole batch
            if (tid == 0) g_cnt[b] = 0;
            for (int i = tid; i < FBBINS; i += TPB) g_fbhist[b][i] = 0;
            __syncthreads();
            const float* rowp = sampled + (size_t)b * Nn * Vn;
            for (int i = tid; i < Nn * Vn; i += TPB) {
                float p = rowp[i] * s_par[i / Vn];
                unsigned bin = __float_as_uint(p) >> 16;
                if (bin >= FBBINS) bin = FBBINS - 1;
                atomicAdd(&g_fbhist[b][bin], 1u);
            }
            __syncthreads();
            __shared__ unsigned s_th;
            if (tid == 0) {
                unsigned cum = 0; unsigned t = 0;
                for (int bin = FBBINS - 1; bin >= 0; bin--) {
                    cum += g_fbhist[b][bin];
                    if (cum >= Kk) { t = (unsigned)bin; break; }
                }
                s_th = t << 16;
            }
            __syncthreads();
            const unsigned th = s_th;
            for (int i = tid; i < Nn * Vn; i += TPB) {
                float p = rowp[i] * s_par[i / Vn];
                unsigned bits = __float_as_uint(p);
                if (bits >= th) gpush(b, bits, (unsigned)i);
            }
            __syncthreads();
            cnt = g_cnt[b];
        }
        if (cnt > CAP) cnt = CAP;

        // repeated block argmax over global candidates (any cnt)
        __shared__ unsigned long long warpmax[TPB / 32];
        for (int j = 0; j < Kk; j++) {
            unsigned long long m = 0ull;
            int mpos = -1;
            for (unsigned i = tid; i < cnt; i += TPB) {
                unsigned long long v = __ldcg(&g_cand[b][i]);
                if (v > m) { m = v; mpos = (int)i; }
            }
            unsigned long long wm = m;
            #pragma unroll
            for (int o = 16; o; o >>= 1) {
                unsigned long long o2 = __shfl_down_sync(0xFFFFFFFFu, wm, o);
                if (o2 > wm) wm = o2;
            }
            if ((tid & 31) == 0) warpmax[tid >> 5] = wm;
            __syncthreads();
            if (tid == 0) {
                unsigned long long g2 = warpmax[0];
                #pragma unroll
                for (int w = 1; w < TPB / 32; w++)
                    if (warpmax[w] > g2) g2 = warpmax[w];
                warpmax[0] = g2;
                s_sel[j] = g2;
            }
            __syncthreads();
            unsigned long long gm = warpmax[0];
            if (mpos >= 0 && m == gm) g_cand[b][mpos] = 0ull;
            __syncthreads();
        }
    }

    // Output: 1536 f32 = [token_ids B*K][topk_probs B*K][parents B*K]
    if (tid < Kk) {
        unsigned long long key = s_sel[tid];
        unsigned tok = 0, parenti = 0;
        float prob = 0.0f;
        if (key != 0ull) {
            unsigned idx = 0xFFFFFFFFu - (unsigned)(key & 0xFFFFFFFFull);
            parenti = idx / Vn;
            tok = idx - parenti * Vn;
            prob = __uint_as_float((unsigned)(key >> 32));
        }
        out[b * Kk + tid]               = (float)tok;
        out[Bn * Kk + b * Kk + tid]     = prob;
        out[2 * Bn * Kk + b * Kk + tid] = (float)parenti;
    }

    // Reset for next graph replay (deterministic launch-to-launch state).
    if (tid == 0) { g_cnt[b] = 0; g_done[b] = 0; }
}

// ---------------------------------------------------------------------------
extern "C" void kernel_launch(void* const* d_in, const int* in_sizes, int n_in,
                              void* d_out, int out_size) {
    const float* sampled = (const float*)d_in[0];  // [B, N, V] fp32
    const float* parent  = (const float*)d_in[1];  // [B, N]    fp32
    float* out = (float*)d_out;                    // 3 * B * K float32

    (void)in_sizes; (void)n_in; (void)out_size;

    dim3 g(CH, Bn);
    keagle<<<g, TPB>>>(out, sampled, parent);
}

// round 10
// speedup vs baseline: 15.9137x; 1.0782x over previous
#include <cuda_runtime.h>
#include <cstdint>

// Fixed shapes from reference setup_inputs
#define Bn 8
#define Nn 64
#define Vn 128000
#define Kk 64
#define CAP 16384
#define ROW_F4 32000                 // float4 per (b,n) row (V/4)
#define CH 16                        // chunks (blocks) per batch
#define CHUNK_F4 (ROW_F4 / CH)       // 2000 float4 per chunk
#define RANKMAX 512                  // rank-select ceiling
#define SCAPB 1024                   // per-block shared candidate capacity
#define FBBINS 16384
#define TPB 256

// Device scratch (no allocation allowed). Counters reset at end of launch.
__device__ unsigned g_cnt[Bn];
__device__ unsigned g_done[Bn];
__device__ unsigned long long g_cand[Bn][CAP];
__device__ unsigned g_fbhist[Bn][FBBINS];

__device__ __forceinline__ unsigned long long mkkey(unsigned bits, unsigned idx) {
    // key = bits<<32 | ~idx : desc key order == value desc, index asc
    // == exact jax.lax.top_k tie-break. Real keys > 0 (value bits > 0).
    return ((unsigned long long)bits << 32) |
           (unsigned long long)(0xFFFFFFFFu - idx);
}

__device__ __forceinline__ void gpush(int b, unsigned long long key) {
    unsigned pos = atomicAdd(&g_cnt[b], 1u);
    if (pos < CAP) g_cand[b][pos] = key;
}

// ---------------------------------------------------------------------------
// Single fused kernel. Grid (CH, Bn) = 128 blocks x 256 threads (one wave).
// Phase A: analytic cut -> stream own chunk of active rows -> candidates to
//   SHARED buffer -> one global atomic per block reserves a range -> STG.
// Phase B (last block per batch): validate -> rank-select top-K (or exact
//   fallback) -> output -> reset counters.
// ---------------------------------------------------------------------------
__global__ __launch_bounds__(TPB) void keagle(float* __restrict__ out,
                                              const float* __restrict__ sampled,
                                              const float* __restrict__ parent) {
    const int b = blockIdx.y;
    const int tid = threadIdx.x;

    __shared__ float s_par[Nn];
    __shared__ float s_cut;
    __shared__ unsigned s_na, s_rank, s_bcnt, s_base;
    __shared__ unsigned char s_rows[Nn];
    __shared__ unsigned long long s_buf[SCAPB];

    if (tid == 0) { s_na = 0; s_bcnt = 0; }
    if (tid < Nn) s_par[tid] = parent[b * Nn + tid];
    __syncthreads();

    // cutf = pmax * (1 - 128/V): ~Binomial(V,128/V) candidates from the top
    // row (mean 128, P(<64) ~ 1e-8; exact fallback backstops).
    if (tid < 32) {
        float pm = fmaxf(s_par[tid], s_par[tid + 32]);
        #pragma unroll
        for (int o = 16; o; o >>= 1)
            pm = fmaxf(pm, __shfl_xor_sync(0xFFFFFFFFu, pm, o));
        if (tid == 0) s_cut = pm * (1.0f - 128.0f / (float)Vn);
    }
    __syncthreads();
    const float cutf = s_cut;

    // Active rows: pp >= cutf (v<1 => RN(v*pp) <= pp < cutf for others).
    if (tid < Nn && s_par[tid] >= cutf) {
        unsigned r = atomicAdd(&s_na, 1u);
        s_rows[r] = (unsigned char)tid;
    }
    __syncthreads();
    const unsigned na = s_na;
    const int base = blockIdx.x * CHUNK_F4;

    // Phase A: stream own chunk of each active row (typically 1 row).
    for (unsigned a = 0; a < na; a++) {
        const int n = s_rows[a];
        const float pp = s_par[n];
        const float4* src = (const float4*)sampled +
                            ((size_t)(b * Nn + n)) * ROW_F4 + base;
        const unsigned colbase = (unsigned)n * (unsigned)Vn + 4u * (unsigned)base;
        const float4 z = make_float4(0.f, 0.f, 0.f, 0.f);

        #pragma unroll
        for (int k = 0; k < 2; k++) {
            int i0 = k * 1024 + tid;
            int i1 = i0 + 256, i2 = i0 + 512, i3 = i0 + 768;
            float4 x0 = (i0 < CHUNK_F4) ? src[i0] : z;
            float4 x1 = (i1 < CHUNK_F4) ? src[i1] : z;
            float4 x2 = (i2 < CHUNK_F4) ? src[i2] : z;
            float4 x3 = (i3 < CHUNK_F4) ? src[i3] : z;
            float m0 = fmaxf(fmaxf(x0.x, x0.y), fmaxf(x0.z, x0.w));
            float m1 = fmaxf(fmaxf(x1.x, x1.y), fmaxf(x1.z, x1.w));
            float m2 = fmaxf(fmaxf(x2.x, x2.y), fmaxf(x2.z, x2.w));
            float m3 = fmaxf(fmaxf(x3.x, x3.y), fmaxf(x3.z, x3.w));
            float m = fmaxf(fmaxf(m0, m1), fmaxf(m2, m3));
            // Exact screen: RN monotone => some elem passes iff max passes.
            if (m * pp >= cutf) {                       // rare
                const float4 xs[4] = {x0, x1, x2, x3};
                const int is[4] = {i0, i1, i2, i3};
                #pragma unroll
                for (int u = 0; u < 4; u++) {
                    float q0 = xs[u].x * pp, q1 = xs[u].y * pp;
                    float q2 = xs[u].z * pp, q3 = xs[u].w * pp;
                    unsigned c = colbase + 4u * (unsigned)is[u];
                    if (q0 >= cutf) { unsigned p_ = atomicAdd(&s_bcnt, 1u);
                        unsigned long long k_ = mkkey(__float_as_uint(q0), c + 0);
                        if (p_ < SCAPB) s_buf[p_] = k_; else gpush(b, k_); }
                    if (q1 >= cutf) { unsigned p_ = atomicAdd(&s_bcnt, 1u);
                        unsigned long long k_ = mkkey(__float_as_uint(q1), c + 1);
                        if (p_ < SCAPB) s_buf[p_] = k_; else gpush(b, k_); }
                    if (q2 >= cutf) { unsigned p_ = atomicAdd(&s_bcnt, 1u);
                        unsigned long long k_ = mkkey(__float_as_uint(q2), c + 2);
                        if (p_ < SCAPB) s_buf[p_] = k_; else gpush(b, k_); }
                    if (q3 >= cutf) { unsigned p_ = atomicAdd(&s_bcnt, 1u);
                        unsigned long long k_ = mkkey(__float_as_uint(q3), c + 3);
                        if (p_ < SCAPB) s_buf[p_] = k_; else gpush(b, k_); }
                }
            }
        }
    }
    __syncthreads();

    // Drain shared buffer with ONE global atomic per block.
    unsigned bcnt = s_bcnt;
    if (bcnt > SCAPB) bcnt = SCAPB;      // overflow already pushed directly
    if (bcnt) {
        if (tid == 0) s_base = atomicAdd(&g_cnt[b], bcnt);
        __syncthreads();
        unsigned gb = s_base;
        for (unsigned i = tid; i < bcnt; i += TPB) {
            unsigned pos = gb + i;
            if (pos < CAP) g_cand[b][pos] = s_buf[i];
        }
    }

    // Handoff: last block of this batch performs selection.
    __threadfence();
    __syncthreads();
    if (tid == 0) s_rank = atomicAdd(&g_done[b], 1u);
    __syncthreads();
    if (s_rank != CH - 1) return;
    __threadfence();

    unsigned cnt = __ldcg(&g_cnt[b]);

    __shared__ unsigned long long s_sel[Kk];

    if (cnt >= Kk && cnt <= RANKMAX) {
        // ---- fast path: rank selection (3 barriers total) ----
        for (unsigned i = tid; i < cnt; i += TPB)
            s_buf[i] = __ldcg(&g_cand[b][i]);
        __syncthreads();
        for (unsigned i = tid; i < cnt; i += TPB) {
            unsigned long long me = s_buf[i];
            int r = 0;
            for (unsigned j = 0; j < cnt; j++) r += (s_buf[j] > me);
            if (r < Kk) s_sel[r] = me;     // ranks unique (keys unique)
        }
        __syncthreads();
    } else {
        // ---- backstop paths (statistically never taken) ----
        if (cnt < Kk) {
            // exact histogram re-pass over the whole batch
            if (tid == 0) g_cnt[b] = 0;
            for (int i = tid; i < FBBINS; i += TPB) g_fbhist[b][i] = 0;
            __syncthreads();
            const float* rowp = sampled + (size_t)b * Nn * Vn;
            for (int i = tid; i < Nn * Vn; i += TPB) {
                float p = rowp[i] * s_par[i / Vn];
                unsigned bin = __float_as_uint(p) >> 16;
                if (bin >= FBBINS) bin = FBBINS - 1;
                atomicAdd(&g_fbhist[b][bin], 1u);
            }
            __syncthreads();
            __shared__ unsigned s_th;
            if (tid == 0) {
                unsigned cum = 0; unsigned t = 0;
                for (int bin = FBBINS - 1; bin >= 0; bin--) {
                    cum += g_fbhist[b][bin];
                    if (cum >= Kk) { t = (unsigned)bin; break; }
                }
                s_th = t << 16;
            }
            __syncthreads();
            const unsigned th = s_th;
            for (int i = tid; i < Nn * Vn; i += TPB) {
                float p = rowp[i] * s_par[i / Vn];
                unsigned bits = __float_as_uint(p);
                if (bits >= th) gpush(b, mkkey(bits, (unsigned)i));
            }
            __syncthreads();
            cnt = g_cnt[b];
        }
        if (cnt > CAP) cnt = CAP;

        // repeated block argmax over global candidates (any cnt)
        __shared__ unsigned long long warpmax[TPB / 32];
        for (int j = 0; j < Kk; j++) {
            unsigned long long m = 0ull;
            int mpos = -1;
            for (unsigned i = tid; i < cnt; i += TPB) {
                unsigned long long v = __ldcg(&g_cand[b][i]);
                if (v > m) { m = v; mpos = (int)i; }
            }
            unsigned long long wm = m;
            #pragma unroll
            for (int o = 16; o; o >>= 1) {
                unsigned long long o2 = __shfl_down_sync(0xFFFFFFFFu, wm, o);
                if (o2 > wm) wm = o2;
            }
            if ((tid & 31) == 0) warpmax[tid >> 5] = wm;
            __syncthreads();
            if (tid == 0) {
                unsigned long long g2 = warpmax[0];
                #pragma unroll
                for (int w = 1; w < TPB / 32; w++)
                    if (warpmax[w] > g2) g2 = warpmax[w];
                warpmax[0] = g2;
                s_sel[j] = g2;
            }
            __syncthreads();
            unsigned long long gm = warpmax[0];
            if (mpos >= 0 && m == gm) g_cand[b][mpos] = 0ull;
            __syncthreads();
        }
    }

    // Output: 1536 f32 = [token_ids B*K][topk_probs B*K][parents B*K]
    if (tid < Kk) {
        unsigned long long key = s_sel[tid];
        unsigned tok = 0, parenti = 0;
        float prob = 0.0f;
        if (key != 0ull) {
            unsigned idx = 0xFFFFFFFFu - (unsigned)(key & 0xFFFFFFFFull);
            parenti = idx / Vn;
            tok = idx - parenti * Vn;
            prob = __uint_as_float((unsigned)(key >> 32));
        }
        out[b * Kk + tid]               = (float)tok;
        out[Bn * Kk + b * Kk + tid]     = prob;
        out[2 * Bn * Kk + b * Kk + tid] = (float)parenti;
    }

    // Reset for next graph replay (deterministic launch-to-launch state).
    if (tid == 0) { g_cnt[b] = 0; g_done[b] = 0; }
}

// ---------------------------------------------------------------------------
extern "C" void kernel_launch(void* const* d_in, const int* in_sizes, int n_in,
                              void* d_out, int out_size) {
    const float* sampled = (const float*)d_in[0];  // [B, N, V] fp32
    const float* parent  = (const float*)d_in[1];  // [B, N]    fp32
    float* out = (float*)d_out;                    // 3 * B * K float32

    (void)in_sizes; (void)n_in; (void)out_size;

    dim3 g(CH, Bn);
    keagle<<<g, TPB>>>(out, sampled, parent);
}

// round 11
// speedup vs baseline: 17.1628x; 1.0785x over previous
#include <cuda_runtime.h>
#include <cstdint>

// Fixed shapes from reference setup_inputs
#define Bn 8
#define Nn 64
#define Vn 128000
#define Kk 64
#define CAP 16384
#define ROW_F4 32000                 // float4 per (b,n) row (V/4)
#define CH 16                        // chunks (blocks) per batch
#define CHUNK_F4 (ROW_F4 / CH)       // 2000 float4 per chunk
#define RANKMAX 512                  // rank-select ceiling
#define SCAPB 1024                   // per-block shared candidate capacity
#define FBBINS 16384
#define TPB 256

// Device scratch (no allocation allowed). Counters reset at end of launch.
__device__ unsigned g_cnt[Bn];
__device__ unsigned g_done[Bn];
__device__ unsigned long long g_cand[Bn][CAP];
__device__ unsigned g_fbhist[Bn][FBBINS];

__device__ __forceinline__ unsigned long long mkkey(unsigned bits, unsigned idx) {
    // key = bits<<32 | ~idx : desc key order == value desc, index asc
    // == exact jax.lax.top_k tie-break. Real keys > 0 (value bits > 0).
    return ((unsigned long long)bits << 32) |
           (unsigned long long)(0xFFFFFFFFu - idx);
}

__device__ __forceinline__ void gpush(int b, unsigned long long key) {
    unsigned pos = atomicAdd(&g_cnt[b], 1u);
    if (pos < CAP) g_cand[b][pos] = key;
}

// ---------------------------------------------------------------------------
// Single fused kernel. Grid (CH, Bn) = 128 blocks x 256 threads (one wave).
// Phase A: analytic cut -> stream own chunk of active rows with 8 parallel
//   loads (MLP=8, one DRAM latency) -> candidates to SHARED -> one global
//   atomic per block reserves a range -> STG drain.
// Phase B (last block per batch): validate -> rank-select top-K (or exact
//   fallback) -> output -> reset counters.
// ---------------------------------------------------------------------------
__global__ __launch_bounds__(TPB) void keagle(float* __restrict__ out,
                                              const float* __restrict__ sampled,
                                              const float* __restrict__ parent) {
    const int b = blockIdx.y;
    const int tid = threadIdx.x;

    __shared__ float s_par[Nn];
    __shared__ float s_cut;
    __shared__ unsigned s_na, s_rank, s_bcnt, s_base;
    __shared__ unsigned char s_rows[Nn];
    __shared__ unsigned long long s_buf[SCAPB];

    if (tid == 0) { s_na = 0; s_bcnt = 0; }
    if (tid < Nn) s_par[tid] = parent[b * Nn + tid];
    __syncthreads();

    // cutf = pmax * (1 - 128/V): ~Binomial(V,128/V) candidates from the top
    // row (mean 128, P(<64) ~ 1e-8; exact fallback backstops).
    if (tid < 32) {
        float pm = fmaxf(s_par[tid], s_par[tid + 32]);
        #pragma unroll
        for (int o = 16; o; o >>= 1)
            pm = fmaxf(pm, __shfl_xor_sync(0xFFFFFFFFu, pm, o));
        if (tid == 0) s_cut = pm * (1.0f - 128.0f / (float)Vn);
    }
    __syncthreads();
    const float cutf = s_cut;

    // Active rows: pp >= cutf (v<1 => RN(v*pp) <= pp < cutf for others).
    if (tid < Nn && s_par[tid] >= cutf) {
        unsigned r = atomicAdd(&s_na, 1u);
        s_rows[r] = (unsigned char)tid;
    }
    __syncthreads();
    const unsigned na = s_na;
    const int base = blockIdx.x * CHUNK_F4;

    // Phase A: stream own chunk of each active row (typically 1 row).
    // All 8 loads issued independently (MLP=8) -> single DRAM round-trip.
    for (unsigned a = 0; a < na; a++) {
        const int n = s_rows[a];
        const float pp = s_par[n];
        const float4* src = (const float4*)sampled +
                            ((size_t)(b * Nn + n)) * ROW_F4 + base;
        const unsigned colbase = (unsigned)n * (unsigned)Vn + 4u * (unsigned)base;
        const float4 z = make_float4(0.f, 0.f, 0.f, 0.f);

        float4 x[8];
        #pragma unroll
        for (int j = 0; j < 8; j++) {
            int idx = tid + j * TPB;                   // 2048 covers 2000
            x[j] = (idx < CHUNK_F4) ? src[idx] : z;
        }
        float m = 0.0f;
        #pragma unroll
        for (int j = 0; j < 8; j++)
            m = fmaxf(m, fmaxf(fmaxf(x[j].x, x[j].y), fmaxf(x[j].z, x[j].w)));

        // Exact screen: RN monotone => some elem passes iff the max passes.
        if (m * pp >= cutf) {                          // rare (~3%/thread)
            #pragma unroll
            for (int j = 0; j < 8; j++) {
                float q0 = x[j].x * pp, q1 = x[j].y * pp;
                float q2 = x[j].z * pp, q3 = x[j].w * pp;
                unsigned c = colbase + 4u * (unsigned)(tid + j * TPB);
                if (q0 >= cutf) { unsigned p_ = atomicAdd(&s_bcnt, 1u);
                    unsigned long long k_ = mkkey(__float_as_uint(q0), c + 0);
                    if (p_ < SCAPB) s_buf[p_] = k_; else gpush(b, k_); }
                if (q1 >= cutf) { unsigned p_ = atomicAdd(&s_bcnt, 1u);
                    unsigned long long k_ = mkkey(__float_as_uint(q1), c + 1);
                    if (p_ < SCAPB) s_buf[p_] = k_; else gpush(b, k_); }
                if (q2 >= cutf) { unsigned p_ = atomicAdd(&s_bcnt, 1u);
                    unsigned long long k_ = mkkey(__float_as_uint(q2), c + 2);
                    if (p_ < SCAPB) s_buf[p_] = k_; else gpush(b, k_); }
                if (q3 >= cutf) { unsigned p_ = atomicAdd(&s_bcnt, 1u);
                    unsigned long long k_ = mkkey(__float_as_uint(q3), c + 3);
                    if (p_ < SCAPB) s_buf[p_] = k_; else gpush(b, k_); }
            }
        }
    }
    __syncthreads();

    // Drain shared buffer with ONE global atomic per block.
    unsigned bcnt = s_bcnt;
    if (bcnt > SCAPB) bcnt = SCAPB;      // overflow already pushed directly
    if (bcnt) {
        if (tid == 0) s_base = atomicAdd(&g_cnt[b], bcnt);
        __syncthreads();
        unsigned gb = s_base;
        for (unsigned i = tid; i < bcnt; i += TPB) {
            unsigned pos = gb + i;
            if (pos < CAP) g_cand[b][pos] = s_buf[i];
        }
    }

    // Handoff: last block of this batch performs selection.
    __threadfence();
    __syncthreads();
    if (tid == 0) s_rank = atomicAdd(&g_done[b], 1u);
    __syncthreads();
    if (s_rank != CH - 1) return;
    __threadfence();

    unsigned cnt = __ldcg(&g_cnt[b]);

    __shared__ unsigned long long s_sel[Kk];

    if (cnt >= Kk && cnt <= RANKMAX) {
        // ---- fast path: rank selection (3 barriers total) ----
        for (unsigned i = tid; i < cnt; i += TPB)
            s_buf[i] = __ldcg(&g_cand[b][i]);
        __syncthreads();
        for (unsigned i = tid; i < cnt; i += TPB) {
            unsigned long long me = s_buf[i];
            int r = 0;
            for (unsigned j = 0; j < cnt; j++) r += (s_buf[j] > me);
            if (r < Kk) s_sel[r] = me;     // ranks unique (keys unique)
        }
        __syncthreads();
    } else {
        // ---- backstop paths (statistically never taken) ----
        if (cnt < Kk) {
            // exact histogram re-pass over the whole batch
            if (tid == 0) g_cnt[b] = 0;
            for (int i = tid; i < FBBINS; i += TPB) g_fbhist[b][i] = 0;
            __syncthreads();
            const float* rowp = sampled + (size_t)b * Nn * Vn;
            for (int i = tid; i < Nn * Vn; i += TPB) {
                float p = rowp[i] * s_par[i / Vn];
                unsigned bin = __float_as_uint(p) >> 16;
                if (bin >= FBBINS) bin = FBBINS - 1;
                atomicAdd(&g_fbhist[b][bin], 1u);
            }
            __syncthreads();
            __shared__ unsigned s_th;
            if (tid == 0) {
                unsigned cum = 0; unsigned t = 0;
                for (int bin = FBBINS - 1; bin >= 0; bin--) {
                    cum += g_fbhist[b][bin];
                    if (cum >= Kk) { t = (unsigned)bin; break; }
                }
                s_th = t << 16;
            }
            __syncthreads();
            const unsigned th = s_th;
            for (int i = tid; i < Nn * Vn; i += TPB) {
                float p = rowp[i] * s_par[i / Vn];
                unsigned bits = __float_as_uint(p);
                if (bits >= th) gpush(b, mkkey(bits, (unsigned)i));
            }
            __syncthreads();
            cnt = g_cnt[b];
        }
        if (cnt > CAP) cnt = CAP;

        // repeated block argmax over global candidates (any cnt)
        __shared__ unsigned long long warpmax[TPB / 32];
        for (int j = 0; j < Kk; j++) {
            unsigned long long m = 0ull;
            int mpos = -1;
            for (unsigned i = tid; i < cnt; i += TPB) {
                unsigned long long v = __ldcg(&g_cand[b][i]);
                if (v > m) { m = v; mpos = (int)i; }
            }
            unsigned long long wm = m;
            #pragma unroll
            for (int o = 16; o; o >>= 1) {
                unsigned long long o2 = __shfl_down_sync(0xFFFFFFFFu, wm, o);
                if (o2 > wm) wm = o2;
            }
            if ((tid & 31) == 0) warpmax[tid >> 5] = wm;
            __syncthreads();
            if (tid == 0) {
                unsigned long long g2 = warpmax[0];
                #pragma unroll
                for (int w = 1; w < TPB / 32; w++)
                    if (warpmax[w] > g2) g2 = warpmax[w];
                warpmax[0] = g2;
                s_sel[j] = g2;
            }
            __syncthreads();
            unsigned long long gm = warpmax[0];
            if (mpos >= 0 && m == gm) g_cand[b][mpos] = 0ull;
            __syncthreads();
        }
    }

    // Output: 1536 f32 = [token_ids B*K][topk_probs B*K][parents B*K]
    if (tid < Kk) {
        unsigned long long key = s_sel[tid];
        unsigned tok = 0, parenti = 0;
        float prob = 0.0f;
        if (key != 0ull) {
            unsigned idx = 0xFFFFFFFFu - (unsigned)(key & 0xFFFFFFFFull);
            parenti = idx / Vn;
            tok = idx - parenti * Vn;
            prob = __uint_as_float((unsigned)(key >> 32));
        }
        out[b * Kk + tid]               = (float)tok;
        out[Bn * Kk + b * Kk + tid]     = prob;
        out[2 * Bn * Kk + b * Kk + tid] = (float)parenti;
    }

    // Reset for next graph replay (deterministic launch-to-launch state).
    if (tid == 0) { g_cnt[b] = 0; g_done[b] = 0; }
}

// ---------------------------------------------------------------------------
extern "C" void kernel_launch(void* const* d_in, const int* in_sizes, int n_in,
                              void* d_out, int out_size) {
    const float* sampled = (const float*)d_in[0];  // [B, N, V] fp32
    const float* parent  = (const float*)d_in[1];  // [B, N]    fp32
    float* out = (float*)d_out;                    // 3 * B * K float32

    (void)in_sizes; (void)n_in; (void)out_size;

    dim3 g(CH, Bn);
    keagle<<<g, TPB>>>(out, sampled, parent);
}